// round 2
// baseline (speedup 1.0000x reference)
#include <cuda_runtime.h>
#include <math.h>

// Problem constants (fixed shapes per reference)
#define NN   20000
#define EE   320000
#define ETOT (EE + NN)     // edges + self loops

// ---------------- scratch (device globals; no allocation allowed) ----------
__device__ float g_comb[NN * 192];
__device__ float g_x0  [NN * 128];
__device__ float g_xl1 [NN * 512];
__device__ float g_xr1 [NN * 512];
__device__ float g_e1  [ETOT * 4];
__device__ float g_m1  [NN * 4];
__device__ float g_s1  [NN * 4];
__device__ float g_agg1[NN * 512];
__device__ float g_xl2 [NN * 128];
__device__ float g_xr2 [NN * 128];
__device__ float g_e2  [ETOT];
__device__ float g_m2  [NN];
__device__ float g_s2  [NN];
__device__ float g_agg2[NN * 128];

// ---------------- helpers ---------------------------------------------------
__device__ __forceinline__ void atomicMaxFloat(float* addr, float val) {
    if (val >= 0.f) atomicMax((int*)addr, __float_as_int(val));
    else            atomicMin((unsigned int*)addr, __float_as_uint(val));
}

// ---------------- kernels ---------------------------------------------------

// combined[n, 0:128] = emb[id[n]], combined[n, 128:192] = feats
__global__ void k_combined(const float* __restrict__ xp, const float* __restrict__ emb,
                           float* __restrict__ comb, int n) {
    int i = blockIdx.x * blockDim.x + threadIdx.x;
    if (i >= n * 192) return;
    int r = i / 192, c = i % 192;
    float v;
    if (c < 128) {
        int id = (int)xp[(size_t)r * 65];
        v = emb[(size_t)id * 128 + c];
    } else {
        v = xp[(size_t)r * 65 + 1 + (c - 128)];
    }
    comb[i] = v;
}

// C[M,N] = act(A[M,K] @ B[K,N] + bias). Requires N%64==0, K%16==0.
__global__ void k_gemm(const float* __restrict__ A, const float* __restrict__ B,
                       const float* __restrict__ bias, float* __restrict__ C,
                       int M, int N, int K, int relu) {
    __shared__ float As[16][64];
    __shared__ float Bs[16][64];
    int tid = threadIdx.x;                 // 256 threads
    int tx = tid & 15, ty = tid >> 4;      // 16x16 thread grid, 4x4 each
    int bm = blockIdx.y * 64, bn = blockIdx.x * 64;
    float acc[4][4] = {};

    int arow = tid >> 2, acol = (tid & 3) * 4;   // A tile 64x16
    int brow = tid >> 4, bcol = (tid & 15) * 4;  // B tile 16x64
    bool aok = (bm + arow) < M;
    const float* Aptr = A + (size_t)(bm + arow) * K + acol;

    for (int k0 = 0; k0 < K; k0 += 16) {
        float4 av = aok ? *(const float4*)(Aptr + k0) : make_float4(0.f, 0.f, 0.f, 0.f);
        As[acol + 0][arow] = av.x;
        As[acol + 1][arow] = av.y;
        As[acol + 2][arow] = av.z;
        As[acol + 3][arow] = av.w;
        *(float4*)&Bs[brow][bcol] = *(const float4*)(B + (size_t)(k0 + brow) * N + bn + bcol);
        __syncthreads();
#pragma unroll
        for (int kk = 0; kk < 16; kk++) {
            float4 a = *(float4*)&As[kk][ty * 4];
            float4 b = *(float4*)&Bs[kk][tx * 4];
            acc[0][0] += a.x * b.x; acc[0][1] += a.x * b.y; acc[0][2] += a.x * b.z; acc[0][3] += a.x * b.w;
            acc[1][0] += a.y * b.x; acc[1][1] += a.y * b.y; acc[1][2] += a.y * b.z; acc[1][3] += a.y * b.w;
            acc[2][0] += a.z * b.x; acc[2][1] += a.z * b.y; acc[2][2] += a.z * b.z; acc[2][3] += a.z * b.w;
            acc[3][0] += a.w * b.x; acc[3][1] += a.w * b.y; acc[3][2] += a.w * b.z; acc[3][3] += a.w * b.w;
        }
        __syncthreads();
    }
#pragma unroll
    for (int i = 0; i < 4; i++) {
        int r = bm + ty * 4 + i;
        if (r >= M) break;
#pragma unroll
        for (int j = 0; j < 4; j++) {
            int c = bn + tx * 4 + j;
            float v = acc[i][j];
            if (bias) v += bias[c];
            if (relu) v = fmaxf(v, 0.f);
            C[(size_t)r * N + c] = v;
        }
    }
}

__global__ void k_fill(float* p, float v, int n) {
    int i = blockIdx.x * blockDim.x + threadIdx.x;
    if (i < n) p[i] = v;
}

// ----- layer 1 (4 heads x 128ch) -----
__global__ void k_att1(const float* __restrict__ xl, const float* __restrict__ xr,
                       const int* __restrict__ ei, const float* __restrict__ att,
                       float* __restrict__ e, int ne, int nn) {
    int warp = (blockIdx.x * blockDim.x + threadIdx.x) >> 5;
    int lane = threadIdx.x & 31;
    int tot = ne + nn;
    if (warp >= tot) return;
    int s, d;
    if (warp < ne) { s = ei[warp]; d = ei[ne + warp]; } else { s = d = warp - ne; }
    const float* pl = xl + (size_t)s * 512;
    const float* pr = xr + (size_t)d * 512;
#pragma unroll
    for (int h = 0; h < 4; h++) {
        float acc = 0.f;
#pragma unroll
        for (int j = 0; j < 4; j++) {
            int c = h * 128 + j * 32 + lane;
            float v = pl[c] + pr[c];
            v = v > 0.f ? v : 0.2f * v;
            acc += v * att[c];
        }
#pragma unroll
        for (int o = 16; o; o >>= 1) acc += __shfl_down_sync(0xffffffffu, acc, o);
        if (!lane) e[(size_t)warp * 4 + h] = acc;
    }
}

__global__ void k_max1(const int* __restrict__ ei, const float* __restrict__ e,
                       float* __restrict__ m, int ne, int nn) {
    int i = blockIdx.x * blockDim.x + threadIdx.x;
    int tot = (ne + nn) * 4;
    if (i >= tot) return;
    int edge = i >> 2, h = i & 3;
    int d = (edge < ne) ? ei[ne + edge] : edge - ne;
    atomicMaxFloat(&m[d * 4 + h], e[i]);
}

__global__ void k_expsum1(const int* __restrict__ ei, float* __restrict__ e,
                          const float* __restrict__ m, float* __restrict__ s,
                          int ne, int nn) {
    int i = blockIdx.x * blockDim.x + threadIdx.x;
    int tot = (ne + nn) * 4;
    if (i >= tot) return;
    int edge = i >> 2, h = i & 3;
    int d = (edge < ne) ? ei[ne + edge] : edge - ne;
    float ex = __expf(e[i] - m[d * 4 + h]);
    e[i] = ex;
    atomicAdd(&s[d * 4 + h], ex);
}

__global__ void k_agg1(const float* __restrict__ xl, const int* __restrict__ ei,
                       const float* __restrict__ e, const float* __restrict__ s,
                       float* __restrict__ out, int ne, int nn) {
    int t = blockIdx.x * blockDim.x + threadIdx.x;
    int edge = t >> 7, c = t & 127;
    int tot = ne + nn;
    if (edge >= tot) return;
    int sn, dn;
    if (edge < ne) { sn = ei[edge]; dn = ei[ne + edge]; } else { sn = dn = edge - ne; }
    const float* pl = xl + (size_t)sn * 512;
    float* po = out + (size_t)dn * 512;
#pragma unroll
    for (int h = 0; h < 4; h++) {
        float alpha = e[(size_t)edge * 4 + h] / (s[dn * 4 + h] + 1e-16f);
        atomicAdd(po + h * 128 + c, alpha * pl[h * 128 + c]);
    }
}

// ----- layer 2 (1 head x 128ch) -----
__global__ void k_att2(const float* __restrict__ xl, const float* __restrict__ xr,
                       const int* __restrict__ ei, const float* __restrict__ att,
                       float* __restrict__ e, int ne, int nn) {
    int warp = (blockIdx.x * blockDim.x + threadIdx.x) >> 5;
    int lane = threadIdx.x & 31;
    int tot = ne + nn;
    if (warp >= tot) return;
    int s, d;
    if (warp < ne) { s = ei[warp]; d = ei[ne + warp]; } else { s = d = warp - ne; }
    const float* pl = xl + (size_t)s * 128;
    const float* pr = xr + (size_t)d * 128;
    float acc = 0.f;
#pragma unroll
    for (int j = 0; j < 4; j++) {
        int c = j * 32 + lane;
        float v = pl[c] + pr[c];
        v = v > 0.f ? v : 0.2f * v;
        acc += v * att[c];
    }
#pragma unroll
    for (int o = 16; o; o >>= 1) acc += __shfl_down_sync(0xffffffffu, acc, o);
    if (!lane) e[warp] = acc;
}

__global__ void k_max2(const int* __restrict__ ei, const float* __restrict__ e,
                       float* __restrict__ m, int ne, int nn) {
    int i = blockIdx.x * blockDim.x + threadIdx.x;
    int tot = ne + nn;
    if (i >= tot) return;
    int d = (i < ne) ? ei[ne + i] : i - ne;
    atomicMaxFloat(&m[d], e[i]);
}

__global__ void k_expsum2(const int* __restrict__ ei, float* __restrict__ e,
                          const float* __restrict__ m, float* __restrict__ s,
                          int ne, int nn) {
    int i = blockIdx.x * blockDim.x + threadIdx.x;
    int tot = ne + nn;
    if (i >= tot) return;
    int d = (i < ne) ? ei[ne + i] : i - ne;
    float ex = __expf(e[i] - m[d]);
    e[i] = ex;
    atomicAdd(&s[d], ex);
}

__global__ void k_agg2(const float* __restrict__ xl, const int* __restrict__ ei,
                       const float* __restrict__ e, const float* __restrict__ s,
                       float* __restrict__ out, int ne, int nn) {
    int t = blockIdx.x * blockDim.x + threadIdx.x;
    int edge = t >> 7, c = t & 127;
    int tot = ne + nn;
    if (edge >= tot) return;
    int sn, dn;
    if (edge < ne) { sn = ei[edge]; dn = ei[ne + edge]; } else { sn = dn = edge - ne; }
    float alpha = e[edge] / (s[dn] + 1e-16f);
    atomicAdd(&out[(size_t)dn * 128 + c], alpha * xl[(size_t)sn * 128 + c]);
}

// x[i] = act(x[i] + b[i % dim])
__global__ void k_biasact(float* __restrict__ x, const float* __restrict__ b,
                          int n, int dim, int relu) {
    int i = blockIdx.x * blockDim.x + threadIdx.x;
    if (i >= n * dim) return;
    float v = x[i] + b[i % dim];
    if (relu) v = fmaxf(v, 0.f);
    x[i] = v;
}

// out[n,10] = x[n,128] @ W[128,10] + b
__global__ void k_out(const float* __restrict__ x, const float* __restrict__ W,
                      const float* __restrict__ b, float* __restrict__ out, int n) {
    int i = blockIdx.x * blockDim.x + threadIdx.x;
    if (i >= n * 10) return;
    int r = i / 10, o = i % 10;
    const float* px = x + (size_t)r * 128;
    float acc = b[o];
#pragma unroll
    for (int k = 0; k < 128; k++) acc += px[k] * W[k * 10 + o];
    out[i] = acc;
}

// ---------------- launch ----------------------------------------------------
extern "C" void kernel_launch(void* const* d_in, const int* in_sizes, int n_in,
                              void* d_out, int out_size) {
    const float* xp   = (const float*)d_in[0];
    const int*   ei   = (const int*)  d_in[1];
    const float* emb  = (const float*)d_in[2];
    const float* pW   = (const float*)d_in[3];
    const float* pb   = (const float*)d_in[4];
    const float* W1l  = (const float*)d_in[5];
    const float* W1r  = (const float*)d_in[6];
    const float* att1 = (const float*)d_in[7];
    const float* b1   = (const float*)d_in[8];
    const float* W2l  = (const float*)d_in[9];
    const float* W2r  = (const float*)d_in[10];
    const float* att2 = (const float*)d_in[11];
    const float* b2   = (const float*)d_in[12];
    const float* oW   = (const float*)d_in[13];
    const float* ob   = (const float*)d_in[14];
    float* out = (float*)d_out;

    int n  = in_sizes[0] / 65;
    int ne = in_sizes[1] / 2;
    int et = ne + n;

    float *comb, *x0, *xl1, *xr1, *e1, *m1, *s1, *agg1;
    float *xl2, *xr2, *e2, *m2, *s2, *agg2;
    cudaGetSymbolAddress((void**)&comb, g_comb);
    cudaGetSymbolAddress((void**)&x0,   g_x0);
    cudaGetSymbolAddress((void**)&xl1,  g_xl1);
    cudaGetSymbolAddress((void**)&xr1,  g_xr1);
    cudaGetSymbolAddress((void**)&e1,   g_e1);
    cudaGetSymbolAddress((void**)&m1,   g_m1);
    cudaGetSymbolAddress((void**)&s1,   g_s1);
    cudaGetSymbolAddress((void**)&agg1, g_agg1);
    cudaGetSymbolAddress((void**)&xl2,  g_xl2);
    cudaGetSymbolAddress((void**)&xr2,  g_xr2);
    cudaGetSymbolAddress((void**)&e2,   g_e2);
    cudaGetSymbolAddress((void**)&m2,   g_m2);
    cudaGetSymbolAddress((void**)&s2,   g_s2);
    cudaGetSymbolAddress((void**)&agg2, g_agg2);

    const int TB = 256;

    // node features -> x0
    k_combined<<<(n * 192 + TB - 1) / TB, TB>>>(xp, emb, comb, n);
    {
        dim3 g(128 / 64, (n + 63) / 64);
        k_gemm<<<g, TB>>>(comb, pW, pb, x0, n, 128, 192, 1);
    }

    // layer 1 transforms
    {
        dim3 g(512 / 64, (n + 63) / 64);
        k_gemm<<<g, TB>>>(x0, W1l, nullptr, xl1, n, 512, 128, 0);
        k_gemm<<<g, TB>>>(x0, W1r, nullptr, xr1, n, 512, 128, 0);
    }

    // layer 1 edge phase
    k_att1<<<(et + 7) / 8, TB>>>(xl1, xr1, ei, att1, e1, ne, n);
    k_fill<<<(n * 4 + TB - 1) / TB, TB>>>(m1, -INFINITY, n * 4);
    cudaMemsetAsync(s1, 0, (size_t)n * 4 * sizeof(float));
    cudaMemsetAsync(agg1, 0, (size_t)n * 512 * sizeof(float));
    k_max1<<<(et * 4 + TB - 1) / TB, TB>>>(ei, e1, m1, ne, n);
    k_expsum1<<<(et * 4 + TB - 1) / TB, TB>>>(ei, e1, m1, s1, ne, n);
    k_agg1<<<((size_t)et * 128 + TB - 1) / TB, TB>>>(xl1, ei, e1, s1, agg1, ne, n);
    k_biasact<<<(n * 512 + TB - 1) / TB, TB>>>(agg1, b1, n, 512, 1);

    // layer 2 transforms
    {
        dim3 g(128 / 64, (n + 63) / 64);
        k_gemm<<<g, TB>>>(agg1, W2l, nullptr, xl2, n, 128, 512, 0);
        k_gemm<<<g, TB>>>(agg1, W2r, nullptr, xr2, n, 128, 512, 0);
    }

    // layer 2 edge phase
    k_att2<<<(et + 7) / 8, TB>>>(xl2, xr2, ei, att2, e2, ne, n);
    k_fill<<<(n + TB - 1) / TB, TB>>>(m2, -INFINITY, n);
    cudaMemsetAsync(s2, 0, (size_t)n * sizeof(float));
    cudaMemsetAsync(agg2, 0, (size_t)n * 128 * sizeof(float));
    k_max2<<<(et + TB - 1) / TB, TB>>>(ei, e2, m2, ne, n);
    k_expsum2<<<(et + TB - 1) / TB, TB>>>(ei, e2, m2, s2, ne, n);
    k_agg2<<<((size_t)et * 128 + TB - 1) / TB, TB>>>(xl2, ei, e2, s2, agg2, ne, n);
    k_biasact<<<(n * 128 + TB - 1) / TB, TB>>>(agg2, b2, n, 128, 0);

    // output head
    k_out<<<(n * 10 + TB - 1) / TB, TB>>>(agg2, oW, ob, out, n);
}

// round 3
// speedup vs baseline: 1.1891x; 1.1891x over previous
#include <cuda_runtime.h>
#include <math.h>

// Problem constants (fixed shapes per reference)
#define NN   20000
#define EE   320000
#define ETOT (EE + NN)     // edges + self loops

// ---------------- scratch (device globals; no allocation allowed) ----------
__device__ float g_comb[NN * 192];
__device__ float g_x0  [NN * 128];
__device__ float g_xl1 [NN * 512];
__device__ float g_xr1 [NN * 512];
__device__ float g_e1  [ETOT * 4];
__device__ float g_agg1[NN * 512];
__device__ float g_xl2 [NN * 128];
__device__ float g_xr2 [NN * 128];
__device__ float g_e2  [ETOT];
__device__ float g_agg2[NN * 128];
// CSR scratch
__device__ int   g_deg   [NN + 1];
__device__ int   g_cursor[NN];
__device__ int   g_rowptr[NN + 1];
__device__ int   g_esrc  [ETOT];
__device__ int   g_eid   [ETOT];

// ---------------- node feature assembly -------------------------------------
__global__ void k_combined(const float* __restrict__ xp, const float* __restrict__ emb,
                           float* __restrict__ comb, int n) {
    int i = blockIdx.x * blockDim.x + threadIdx.x;
    if (i >= n * 192) return;
    int r = i / 192, c = i % 192;
    float v;
    if (c < 128) {
        int id = (int)xp[(size_t)r * 65];
        v = emb[(size_t)id * 128 + c];
    } else {
        v = xp[(size_t)r * 65 + 1 + (c - 128)];
    }
    comb[i] = v;
}

// ---------------- GEMM: 128x128 tile, 8x8 per thread -------------------------
// C[M,N] = act(A[M,K] @ B[K,N] + bias). Requires N%128==0, K%8==0.
__global__ void k_gemm(const float* __restrict__ A, const float* __restrict__ B,
                       const float* __restrict__ bias, float* __restrict__ C,
                       int M, int N, int K, int relu) {
    __shared__ float As[8][132];
    __shared__ float Bs[8][132];
    int tid = threadIdx.x;                 // 256 threads
    int tx = tid & 15, ty = tid >> 4;      // 16x16 thread layout
    int bm = blockIdx.y * 128, bn = blockIdx.x * 128;
    float acc[8][8] = {};

    int ar = tid >> 1;            // 0..127 : row within A tile
    int ac = (tid & 1) * 4;       // 0 or 4 : k offset
    int br = tid >> 5;            // 0..7   : k row of B tile
    int bc = (tid & 31) * 4;      // 0..124 : col within B tile
    bool aok = (bm + ar) < M;
    const float* Ap = A + (size_t)(bm + ar) * K + ac;

    for (int k0 = 0; k0 < K; k0 += 8) {
        float4 av = aok ? *(const float4*)(Ap + k0) : make_float4(0.f, 0.f, 0.f, 0.f);
        As[ac + 0][ar] = av.x;
        As[ac + 1][ar] = av.y;
        As[ac + 2][ar] = av.z;
        As[ac + 3][ar] = av.w;
        *(float4*)&Bs[br][bc] = *(const float4*)(B + (size_t)(k0 + br) * N + bn + bc);
        __syncthreads();
#pragma unroll
        for (int kk = 0; kk < 8; kk++) {
            float a[8], b[8];
            *(float4*)(a)     = *(float4*)&As[kk][ty * 4];
            *(float4*)(a + 4) = *(float4*)&As[kk][64 + ty * 4];
            *(float4*)(b)     = *(float4*)&Bs[kk][tx * 4];
            *(float4*)(b + 4) = *(float4*)&Bs[kk][64 + tx * 4];
#pragma unroll
            for (int i = 0; i < 8; i++)
#pragma unroll
                for (int j = 0; j < 8; j++)
                    acc[i][j] += a[i] * b[j];
        }
        __syncthreads();
    }
#pragma unroll
    for (int hi = 0; hi < 2; hi++)
#pragma unroll
    for (int ii = 0; ii < 4; ii++) {
        int r = bm + hi * 64 + ty * 4 + ii;
        if (r >= M) continue;
#pragma unroll
        for (int hj = 0; hj < 2; hj++)
#pragma unroll
        for (int jj = 0; jj < 4; jj++) {
            int c = bn + hj * 64 + tx * 4 + jj;
            float v = acc[hi * 4 + ii][hj * 4 + jj];
            if (bias) v += bias[c];
            if (relu) v = fmaxf(v, 0.f);
            C[(size_t)r * N + c] = v;
        }
    }
}

// ---------------- CSR build --------------------------------------------------
__global__ void k_hist(const int* __restrict__ ei, int* __restrict__ deg, int ne, int nn) {
    int i = blockIdx.x * blockDim.x + threadIdx.x;
    int tot = ne + nn;
    if (i >= tot) return;
    int d = (i < ne) ? ei[ne + i] : i - ne;
    atomicAdd(&deg[d], 1);
}

__global__ void k_scan(const int* __restrict__ deg, int* __restrict__ rowptr, int n) {
    __shared__ int sh[1024];
    __shared__ int carry_s;
    int t = threadIdx.x;
    if (t == 0) carry_s = 0;
    __syncthreads();
    for (int base = 0; base < n; base += 1024) {
        int i = base + t;
        int v = (i < n) ? deg[i] : 0;
        sh[t] = v;
        __syncthreads();
        for (int off = 1; off < 1024; off <<= 1) {
            int add = (t >= off) ? sh[t - off] : 0;
            __syncthreads();
            sh[t] += add;
            __syncthreads();
        }
        if (i < n) rowptr[i] = carry_s + sh[t] - v;   // exclusive
        __syncthreads();
        if (t == 0) carry_s += sh[1023];
        __syncthreads();
    }
    if (t == 0) rowptr[n] = carry_s;
}

__global__ void k_scatter(const int* __restrict__ ei, const int* __restrict__ rowptr,
                          int* __restrict__ cursor, int* __restrict__ esrc,
                          int* __restrict__ eid, int ne, int nn) {
    int i = blockIdx.x * blockDim.x + threadIdx.x;
    int tot = ne + nn;
    if (i >= tot) return;
    int s, d;
    if (i < ne) { s = ei[i]; d = ei[ne + i]; } else { s = d = i - ne; }
    int pos = rowptr[d] + atomicAdd(&cursor[d], 1);
    esrc[pos] = s;
    eid[pos]  = i;
}

// ---------------- attention scores (edge-parallel, warp per edge) ------------
__global__ void k_att1(const float* __restrict__ xl, const float* __restrict__ xr,
                       const int* __restrict__ ei, const float* __restrict__ att,
                       float* __restrict__ e, int ne, int nn) {
    int warp = (blockIdx.x * blockDim.x + threadIdx.x) >> 5;
    int lane = threadIdx.x & 31;
    int tot = ne + nn;
    if (warp >= tot) return;
    int s, d;
    if (warp < ne) { s = ei[warp]; d = ei[ne + warp]; } else { s = d = warp - ne; }
    const float* pl = xl + (size_t)s * 512;
    const float* pr = xr + (size_t)d * 512;
#pragma unroll
    for (int h = 0; h < 4; h++) {
        float acc = 0.f;
#pragma unroll
        for (int j = 0; j < 4; j++) {
            int c = h * 128 + j * 32 + lane;
            float v = pl[c] + pr[c];
            v = v > 0.f ? v : 0.2f * v;
            acc += v * att[c];
        }
#pragma unroll
        for (int o = 16; o; o >>= 1) acc += __shfl_down_sync(0xffffffffu, acc, o);
        if (!lane) e[(size_t)warp * 4 + h] = acc;
    }
}

__global__ void k_att2(const float* __restrict__ xl, const float* __restrict__ xr,
                       const int* __restrict__ ei, const float* __restrict__ att,
                       float* __restrict__ e, int ne, int nn) {
    int warp = (blockIdx.x * blockDim.x + threadIdx.x) >> 5;
    int lane = threadIdx.x & 31;
    int tot = ne + nn;
    if (warp >= tot) return;
    int s, d;
    if (warp < ne) { s = ei[warp]; d = ei[ne + warp]; } else { s = d = warp - ne; }
    const float* pl = xl + (size_t)s * 128;
    const float* pr = xr + (size_t)d * 128;
    float acc = 0.f;
#pragma unroll
    for (int j = 0; j < 4; j++) {
        int c = j * 32 + lane;
        float v = pl[c] + pr[c];
        v = v > 0.f ? v : 0.2f * v;
        acc += v * att[c];
    }
#pragma unroll
    for (int o = 16; o; o >>= 1) acc += __shfl_down_sync(0xffffffffu, acc, o);
    if (!lane) e[warp] = acc;
}

// ---------------- fused softmax + aggregation + bias/act (block per node) ----
// Layer 1: 4 heads x 128 ch. 128 threads: thread t owns channel t of each head.
__global__ void k_sagg1(const float* __restrict__ xl, const int* __restrict__ rowptr,
                        const int* __restrict__ esrc, const int* __restrict__ eid,
                        const float* __restrict__ e1, const float* __restrict__ bias,
                        float* __restrict__ out) {
    int node = blockIdx.x;
    int t = threadIdx.x;             // 128
    int beg = rowptr[node], end = rowptr[node + 1];
    int deg = end - beg;

    __shared__ float red[128];
    __shared__ float salpha[128][4];
    __shared__ int   ssrc[128];
    __shared__ float mh[4], rinv[4];

    // pass 1: per-head max
    float mx[4] = {-INFINITY, -INFINITY, -INFINITY, -INFINITY};
    for (int j = t; j < deg; j += 128) {
        const float* pe = e1 + (size_t)eid[beg + j] * 4;
#pragma unroll
        for (int h = 0; h < 4; h++) mx[h] = fmaxf(mx[h], pe[h]);
    }
#pragma unroll
    for (int h = 0; h < 4; h++) {
        red[t] = mx[h]; __syncthreads();
        for (int off = 64; off; off >>= 1) {
            if (t < off) red[t] = fmaxf(red[t], red[t + off]);
            __syncthreads();
        }
        if (t == 0) mh[h] = red[0];
        __syncthreads();
    }
    // pass 2: per-head sum of exp
    float sm[4] = {0.f, 0.f, 0.f, 0.f};
    for (int j = t; j < deg; j += 128) {
        const float* pe = e1 + (size_t)eid[beg + j] * 4;
#pragma unroll
        for (int h = 0; h < 4; h++) sm[h] += __expf(pe[h] - mh[h]);
    }
#pragma unroll
    for (int h = 0; h < 4; h++) {
        red[t] = sm[h]; __syncthreads();
        for (int off = 64; off; off >>= 1) {
            if (t < off) red[t] += red[t + off];
            __syncthreads();
        }
        if (t == 0) rinv[h] = 1.f / (red[0] + 1e-16f);
        __syncthreads();
    }
    // pass 3: aggregate
    float acc[4] = {0.f, 0.f, 0.f, 0.f};
    for (int base = 0; base < deg; base += 128) {
        int j = base + t;
        if (j < deg) {
            ssrc[t] = esrc[beg + j];
            const float* pe = e1 + (size_t)eid[beg + j] * 4;
#pragma unroll
            for (int h = 0; h < 4; h++)
                salpha[t][h] = __expf(pe[h] - mh[h]) * rinv[h];
        }
        __syncthreads();
        int cnt = min(128, deg - base);
        for (int j2 = 0; j2 < cnt; j2++) {
            const float* row = xl + (size_t)ssrc[j2] * 512;
#pragma unroll
            for (int h = 0; h < 4; h++)
                acc[h] += salpha[j2][h] * row[h * 128 + t];
        }
        __syncthreads();
    }
#pragma unroll
    for (int h = 0; h < 4; h++) {
        int c = h * 128 + t;
        out[(size_t)node * 512 + c] = fmaxf(acc[h] + bias[c], 0.f);   // + relu
    }
}

// Layer 2: 1 head x 128 ch.
__global__ void k_sagg2(const float* __restrict__ xl, const int* __restrict__ rowptr,
                        const int* __restrict__ esrc, const int* __restrict__ eid,
                        const float* __restrict__ e2, const float* __restrict__ bias,
                        float* __restrict__ out) {
    int node = blockIdx.x;
    int t = threadIdx.x;             // 128
    int beg = rowptr[node], end = rowptr[node + 1];
    int deg = end - beg;

    __shared__ float red[128];
    __shared__ float salpha[128];
    __shared__ int   ssrc[128];
    __shared__ float mh, rinv;

    float mx = -INFINITY;
    for (int j = t; j < deg; j += 128) mx = fmaxf(mx, e2[eid[beg + j]]);
    red[t] = mx; __syncthreads();
    for (int off = 64; off; off >>= 1) {
        if (t < off) red[t] = fmaxf(red[t], red[t + off]);
        __syncthreads();
    }
    if (t == 0) mh = red[0];
    __syncthreads();

    float sm = 0.f;
    for (int j = t; j < deg; j += 128) sm += __expf(e2[eid[beg + j]] - mh);
    red[t] = sm; __syncthreads();
    for (int off = 64; off; off >>= 1) {
        if (t < off) red[t] += red[t + off];
        __syncthreads();
    }
    if (t == 0) rinv = 1.f / (red[0] + 1e-16f);
    __syncthreads();

    float acc = 0.f;
    for (int base = 0; base < deg; base += 128) {
        int j = base + t;
        if (j < deg) {
            ssrc[t] = esrc[beg + j];
            salpha[t] = __expf(e2[eid[beg + j]] - mh) * rinv;
        }
        __syncthreads();
        int cnt = min(128, deg - base);
        for (int j2 = 0; j2 < cnt; j2++)
            acc += salpha[j2] * xl[(size_t)ssrc[j2] * 128 + t];
        __syncthreads();
    }
    out[(size_t)node * 128 + t] = acc + bias[t];
}

// out[n,10] = x[n,128] @ W[128,10] + b
__global__ void k_out(const float* __restrict__ x, const float* __restrict__ W,
                      const float* __restrict__ b, float* __restrict__ out, int n) {
    int i = blockIdx.x * blockDim.x + threadIdx.x;
    if (i >= n * 10) return;
    int r = i / 10, o = i % 10;
    const float* px = x + (size_t)r * 128;
    float acc = b[o];
#pragma unroll
    for (int k = 0; k < 128; k++) acc += px[k] * W[k * 10 + o];
    out[i] = acc;
}

// ---------------- launch ----------------------------------------------------
extern "C" void kernel_launch(void* const* d_in, const int* in_sizes, int n_in,
                              void* d_out, int out_size) {
    const float* xp   = (const float*)d_in[0];
    const int*   ei   = (const int*)  d_in[1];
    const float* emb  = (const float*)d_in[2];
    const float* pW   = (const float*)d_in[3];
    const float* pb   = (const float*)d_in[4];
    const float* W1l  = (const float*)d_in[5];
    const float* W1r  = (const float*)d_in[6];
    const float* att1 = (const float*)d_in[7];
    const float* b1   = (const float*)d_in[8];
    const float* W2l  = (const float*)d_in[9];
    const float* W2r  = (const float*)d_in[10];
    const float* att2 = (const float*)d_in[11];
    const float* b2   = (const float*)d_in[12];
    const float* oW   = (const float*)d_in[13];
    const float* ob   = (const float*)d_in[14];
    float* out = (float*)d_out;

    int n  = in_sizes[0] / 65;
    int ne = in_sizes[1] / 2;
    int et = ne + n;

    float *comb, *x0, *xl1, *xr1, *e1, *agg1, *xl2, *xr2, *e2, *agg2;
    int *deg, *cursor, *rowptr, *esrc, *eid;
    cudaGetSymbolAddress((void**)&comb, g_comb);
    cudaGetSymbolAddress((void**)&x0,   g_x0);
    cudaGetSymbolAddress((void**)&xl1,  g_xl1);
    cudaGetSymbolAddress((void**)&xr1,  g_xr1);
    cudaGetSymbolAddress((void**)&e1,   g_e1);
    cudaGetSymbolAddress((void**)&agg1, g_agg1);
    cudaGetSymbolAddress((void**)&xl2,  g_xl2);
    cudaGetSymbolAddress((void**)&xr2,  g_xr2);
    cudaGetSymbolAddress((void**)&e2,   g_e2);
    cudaGetSymbolAddress((void**)&agg2, g_agg2);
    cudaGetSymbolAddress((void**)&deg,    g_deg);
    cudaGetSymbolAddress((void**)&cursor, g_cursor);
    cudaGetSymbolAddress((void**)&rowptr, g_rowptr);
    cudaGetSymbolAddress((void**)&esrc,   g_esrc);
    cudaGetSymbolAddress((void**)&eid,    g_eid);

    const int TB = 256;

    // ---- CSR build (independent of GEMM chain) ----
    cudaMemsetAsync(deg, 0, (size_t)(n + 1) * sizeof(int));
    cudaMemsetAsync(cursor, 0, (size_t)n * sizeof(int));
    k_hist<<<(et + TB - 1) / TB, TB>>>(ei, deg, ne, n);
    k_scan<<<1, 1024>>>(deg, rowptr, n);
    k_scatter<<<(et + TB - 1) / TB, TB>>>(ei, rowptr, cursor, esrc, eid, ne, n);

    // ---- node features -> x0 ----
    k_combined<<<(n * 192 + TB - 1) / TB, TB>>>(xp, emb, comb, n);
    {
        dim3 g(1, (n + 127) / 128);
        k_gemm<<<g, TB>>>(comb, pW, pb, x0, n, 128, 192, 1);
    }

    // ---- layer 1 ----
    {
        dim3 g(4, (n + 127) / 128);
        k_gemm<<<g, TB>>>(x0, W1l, nullptr, xl1, n, 512, 128, 0);
        k_gemm<<<g, TB>>>(x0, W1r, nullptr, xr1, n, 512, 128, 0);
    }
    k_att1<<<(et + 7) / 8, TB>>>(xl1, xr1, ei, att1, e1, ne, n);
    k_sagg1<<<n, 128>>>(xl1, rowptr, esrc, eid, e1, b1, agg1);

    // ---- layer 2 ----
    {
        dim3 g(1, (n + 127) / 128);
        k_gemm<<<g, TB>>>(agg1, W2l, nullptr, xl2, n, 128, 512, 0);
        k_gemm<<<g, TB>>>(agg1, W2r, nullptr, xr2, n, 128, 512, 0);
    }
    k_att2<<<(et + 7) / 8, TB>>>(xl2, xr2, ei, att2, e2, ne, n);
    k_sagg2<<<n, 128>>>(xl2, rowptr, esrc, eid, e2, b2, agg2);

    // ---- output head ----
    k_out<<<(n * 10 + TB - 1) / TB, TB>>>(agg2, oW, ob, out, n);
}

// round 5
// speedup vs baseline: 1.5276x; 1.2847x over previous
#include <cuda_runtime.h>
#include <math.h>

// Problem constants (fixed shapes per reference)
#define NN   20000
#define EE   320000
#define ETOT (EE + NN)     // edges + self loops

// ---------------- scratch (device globals; no allocation allowed) ----------
__device__ float g_x0  [NN * 128];
__device__ float g_xl1 [NN * 512];
__device__ float g_xr1 [NN * 512];
__device__ float g_agg1[NN * 512];
__device__ float g_xl2 [NN * 128];
__device__ float g_xr2 [NN * 128];
__device__ float g_agg2[NN * 128];
// CSR scratch
__device__ int   g_deg   [NN + 1];
__device__ int   g_cursor[NN];
__device__ int   g_rowptr[NN + 1];
__device__ int   g_esrc  [ETOT];

// ---------------- GEMM: 128x128 tile, 8x8 per thread -------------------------
// C[M,N] = act(A[M,K] @ B[K,N] + bias). Requires N%128==0, K%8==0.
// GATHER variant builds A rows on the fly: cols 0..127 = emb[id[r]], cols 128.. = feats.
template <bool GATHER>
__global__ void k_gemm(const float* __restrict__ A, const float* __restrict__ B,
                       const float* __restrict__ bias, float* __restrict__ C,
                       int M, int N, int K, int relu,
                       const float* __restrict__ xp, const float* __restrict__ emb) {
    __shared__ float As[8][132];
    __shared__ float Bs[8][132];
    int tid = threadIdx.x;                 // 256 threads
    int tx = tid & 15, ty = tid >> 4;      // 16x16 thread layout
    int bm = blockIdx.y * 128, bn = blockIdx.x * 128;
    float acc[8][8] = {};

    int ar = tid >> 1;            // 0..127 : row within A tile
    int ac = (tid & 1) * 4;       // 0 or 4 : k offset
    int br = tid >> 5;            // 0..7   : k row of B tile
    int bc = (tid & 31) * 4;      // 0..124 : col within B tile
    bool aok = (bm + ar) < M;
    const float* Ap = GATHER ? nullptr : A + (size_t)(bm + ar) * K + ac;
    int gid = 0;
    if (GATHER && aok) gid = (int)xp[(size_t)(bm + ar) * 65];

    for (int k0 = 0; k0 < K; k0 += 8) {
        float4 av = make_float4(0.f, 0.f, 0.f, 0.f);
        if (aok) {
            if (GATHER) {
                int kc = k0 + ac;
                if (kc < 128) {
                    av = *(const float4*)(emb + (size_t)gid * 128 + kc);
                } else {
                    const float* p = xp + (size_t)(bm + ar) * 65 + 1 + (kc - 128);
                    av = make_float4(p[0], p[1], p[2], p[3]);
                }
            } else {
                av = *(const float4*)(Ap + k0);
            }
        }
        As[ac + 0][ar] = av.x;
        As[ac + 1][ar] = av.y;
        As[ac + 2][ar] = av.z;
        As[ac + 3][ar] = av.w;
        *(float4*)&Bs[br][bc] = *(const float4*)(B + (size_t)(k0 + br) * N + bn + bc);
        __syncthreads();
#pragma unroll
        for (int kk = 0; kk < 8; kk++) {
            float a[8], b[8];
            *(float4*)(a)     = *(float4*)&As[kk][ty * 4];
            *(float4*)(a + 4) = *(float4*)&As[kk][64 + ty * 4];
            *(float4*)(b)     = *(float4*)&Bs[kk][tx * 4];
            *(float4*)(b + 4) = *(float4*)&Bs[kk][64 + tx * 4];
#pragma unroll
            for (int i = 0; i < 8; i++)
#pragma unroll
                for (int j = 0; j < 8; j++)
                    acc[i][j] += a[i] * b[j];
        }
        __syncthreads();
    }
#pragma unroll
    for (int hi = 0; hi < 2; hi++)
#pragma unroll
    for (int ii = 0; ii < 4; ii++) {
        int r = bm + hi * 64 + ty * 4 + ii;
        if (r >= M) continue;
#pragma unroll
        for (int hj = 0; hj < 2; hj++)
#pragma unroll
        for (int jj = 0; jj < 4; jj++) {
            int c = bn + hj * 64 + tx * 4 + jj;
            float v = acc[hi * 4 + ii][hj * 4 + jj];
            if (bias) v += bias[c];
            if (relu) v = fmaxf(v, 0.f);
            C[(size_t)r * N + c] = v;
        }
    }
}

// ---------------- CSR build --------------------------------------------------
__global__ void k_hist(const int* __restrict__ ei, int* __restrict__ deg, int ne, int nn) {
    int i = blockIdx.x * blockDim.x + threadIdx.x;
    int tot = ne + nn;
    if (i >= tot) return;
    int d = (i < ne) ? ei[ne + i] : i - ne;
    atomicAdd(&deg[d], 1);
}

__global__ void k_scan(const int* __restrict__ deg, int* __restrict__ rowptr, int n) {
    __shared__ int sh[1024];
    __shared__ int carry_s;
    int t = threadIdx.x;
    if (t == 0) carry_s = 0;
    __syncthreads();
    for (int base = 0; base < n; base += 1024) {
        int i = base + t;
        int v = (i < n) ? deg[i] : 0;
        sh[t] = v;
        __syncthreads();
        for (int off = 1; off < 1024; off <<= 1) {
            int add = (t >= off) ? sh[t - off] : 0;
            __syncthreads();
            sh[t] += add;
            __syncthreads();
        }
        if (i < n) rowptr[i] = carry_s + sh[t] - v;   // exclusive
        __syncthreads();
        if (t == 0) carry_s += sh[1023];
        __syncthreads();
    }
    if (t == 0) rowptr[n] = carry_s;
}

__global__ void k_scatter(const int* __restrict__ ei, const int* __restrict__ rowptr,
                          int* __restrict__ cursor, int* __restrict__ esrc,
                          int ne, int nn) {
    int i = blockIdx.x * blockDim.x + threadIdx.x;
    int tot = ne + nn;
    if (i >= tot) return;
    int s, d;
    if (i < ne) { s = ei[i]; d = ei[ne + i]; } else { s = d = i - ne; }
    int pos = rowptr[d] + atomicAdd(&cursor[d], 1);
    esrc[pos] = s;
}

// ---------------- fused GATv2 edge phase (flash-style online softmax) --------
// Layer 1: 4 heads x 128 ch. Block = 128 threads (4 warps) per node.
// Each warp processes a strided subset of incoming edges with a private
// running (max, sum, acc) state; states merge through smem at the end.
__global__ void k_fused1(const float* __restrict__ xl, const float* __restrict__ xr,
                         const int* __restrict__ rowptr, const int* __restrict__ esrc,
                         const float* __restrict__ att, const float* __restrict__ bias,
                         float* __restrict__ out) {
    int node = blockIdx.x;
    int t = threadIdx.x, warp = t >> 5, lane = t & 31;
    int beg = rowptr[node], end = rowptr[node + 1];

    float xrv[16], attv[16];
    const float* pxr = xr + (size_t)node * 512;
#pragma unroll
    for (int i = 0; i < 16; i++) {
        int c = i * 32 + lane;
        xrv[i] = pxr[c];
        attv[i] = att[c];
    }
    float m[4] = {-INFINITY, -INFINITY, -INFINITY, -INFINITY};
    float s[4] = {0.f, 0.f, 0.f, 0.f};
    float acc[16] = {};

    for (int j = beg + warp; j < end; j += 4) {
        const float* px = xl + (size_t)esrc[j] * 512;
        float xv[16], p[4] = {0.f, 0.f, 0.f, 0.f};
#pragma unroll
        for (int i = 0; i < 16; i++) {
            xv[i] = px[i * 32 + lane];
            float v = xv[i] + xrv[i];
            v = v > 0.f ? v : 0.2f * v;
            p[i >> 2] += v * attv[i];
        }
#pragma unroll
        for (int o = 16; o; o >>= 1) {
            p[0] += __shfl_xor_sync(0xffffffffu, p[0], o);
            p[1] += __shfl_xor_sync(0xffffffffu, p[1], o);
            p[2] += __shfl_xor_sync(0xffffffffu, p[2], o);
            p[3] += __shfl_xor_sync(0xffffffffu, p[3], o);
        }
#pragma unroll
        for (int h = 0; h < 4; h++) {
            float e = p[h];
            float mn = fmaxf(m[h], e);
            float sc = __expf(m[h] - mn);       // first edge: exp(-inf)=0
            float w  = __expf(e - mn);
            s[h] = s[h] * sc + w;
            m[h] = mn;
#pragma unroll
            for (int i = 0; i < 4; i++) {
                int ii = h * 4 + i;
                acc[ii] = acc[ii] * sc + w * xv[ii];
            }
        }
    }

    __shared__ float sm[4][4], ss[4][4];
    __shared__ float sacc[4][512];
    if (lane < 4) { sm[warp][lane] = m[lane]; ss[warp][lane] = s[lane]; }
#pragma unroll
    for (int i = 0; i < 16; i++) sacc[warp][i * 32 + lane] = acc[i];
    __syncthreads();

#pragma unroll
    for (int h = 0; h < 4; h++) {
        int c = h * 128 + t;
        float M = fmaxf(fmaxf(sm[0][h], sm[1][h]), fmaxf(sm[2][h], sm[3][h]));
        float S = 0.f, A = 0.f;
#pragma unroll
        for (int w = 0; w < 4; w++) {
            float sc = __expf(sm[w][h] - M);    // empty warp: m=-inf -> 0
            S += ss[w][h] * sc;
            A += sacc[w][c] * sc;
        }
        out[(size_t)node * 512 + c] = fmaxf(A / (S + 1e-16f) + bias[c], 0.f);
    }
}

// Layer 2: 1 head x 128 ch.
__global__ void k_fused2(const float* __restrict__ xl, const float* __restrict__ xr,
                         const int* __restrict__ rowptr, const int* __restrict__ esrc,
                         const float* __restrict__ att, const float* __restrict__ bias,
                         float* __restrict__ out) {
    int node = blockIdx.x;
    int t = threadIdx.x, warp = t >> 5, lane = t & 31;
    int beg = rowptr[node], end = rowptr[node + 1];

    float xrv[4], attv[4];
    const float* pxr = xr + (size_t)node * 128;
#pragma unroll
    for (int i = 0; i < 4; i++) {
        int c = i * 32 + lane;
        xrv[i] = pxr[c];
        attv[i] = att[c];
    }
    float m = -INFINITY, s = 0.f;
    float acc[4] = {};

    for (int j = beg + warp; j < end; j += 4) {
        const float* px = xl + (size_t)esrc[j] * 128;
        float xv[4], p = 0.f;
#pragma unroll
        for (int i = 0; i < 4; i++) {
            xv[i] = px[i * 32 + lane];
            float v = xv[i] + xrv[i];
            v = v > 0.f ? v : 0.2f * v;
            p += v * attv[i];
        }
#pragma unroll
        for (int o = 16; o; o >>= 1) p += __shfl_xor_sync(0xffffffffu, p, o);
        float mn = fmaxf(m, p);
        float sc = __expf(m - mn);
        float w  = __expf(p - mn);
        s = s * sc + w;
        m = mn;
#pragma unroll
        for (int i = 0; i < 4; i++) acc[i] = acc[i] * sc + w * xv[i];
    }

    __shared__ float sm[4], ss[4];
    __shared__ float sacc[4][128];
    if (!lane) { sm[warp] = m; ss[warp] = s; }
#pragma unroll
    for (int i = 0; i < 4; i++) sacc[warp][i * 32 + lane] = acc[i];
    __syncthreads();

    float M = fmaxf(fmaxf(sm[0], sm[1]), fmaxf(sm[2], sm[3]));
    float S = 0.f, A = 0.f;
#pragma unroll
    for (int w = 0; w < 4; w++) {
        float sc = __expf(sm[w] - M);
        S += ss[w] * sc;
        A += sacc[w][t] * sc;
    }
    out[(size_t)node * 128 + t] = A / (S + 1e-16f) + bias[t];
}

// out[n,10] = x[n,128] @ W[128,10] + b
__global__ void k_out(const float* __restrict__ x, const float* __restrict__ W,
                      const float* __restrict__ b, float* __restrict__ out, int n) {
    int i = blockIdx.x * blockDim.x + threadIdx.x;
    if (i >= n * 10) return;
    int r = i / 10, o = i % 10;
    const float* px = x + (size_t)r * 128;
    float acc = b[o];
#pragma unroll
    for (int k = 0; k < 128; k++) acc += px[k] * W[k * 10 + o];
    out[i] = acc;
}

// ---------------- launch ----------------------------------------------------
extern "C" void kernel_launch(void* const* d_in, const int* in_sizes, int n_in,
                              void* d_out, int out_size) {
    const float* xp   = (const float*)d_in[0];
    const int*   ei   = (const int*)  d_in[1];
    const float* emb  = (const float*)d_in[2];
    const float* pW   = (const float*)d_in[3];
    const float* pb   = (const float*)d_in[4];
    const float* W1l  = (const float*)d_in[5];
    const float* W1r  = (const float*)d_in[6];
    const float* att1 = (const float*)d_in[7];
    const float* b1   = (const float*)d_in[8];
    const float* W2l  = (const float*)d_in[9];
    const float* W2r  = (const float*)d_in[10];
    const float* att2 = (const float*)d_in[11];
    const float* b2   = (const float*)d_in[12];
    const float* oW   = (const float*)d_in[13];
    const float* ob   = (const float*)d_in[14];
    float* out = (float*)d_out;

    int n  = in_sizes[0] / 65;
    int ne = in_sizes[1] / 2;
    int et = ne + n;

    float *x0, *xl1, *xr1, *agg1, *xl2, *xr2, *agg2;
    int *deg, *cursor, *rowptr, *esrc;
    cudaGetSymbolAddress((void**)&x0,   g_x0);
    cudaGetSymbolAddress((void**)&xl1,  g_xl1);
    cudaGetSymbolAddress((void**)&xr1,  g_xr1);
    cudaGetSymbolAddress((void**)&agg1, g_agg1);
    cudaGetSymbolAddress((void**)&xl2,  g_xl2);
    cudaGetSymbolAddress((void**)&xr2,  g_xr2);
    cudaGetSymbolAddress((void**)&agg2, g_agg2);
    cudaGetSymbolAddress((void**)&deg,    g_deg);
    cudaGetSymbolAddress((void**)&cursor, g_cursor);
    cudaGetSymbolAddress((void**)&rowptr, g_rowptr);
    cudaGetSymbolAddress((void**)&esrc,   g_esrc);

    const int TB = 256;

    // ---- CSR build ----
    cudaMemsetAsync(deg, 0, (size_t)(n + 1) * sizeof(int));
    cudaMemsetAsync(cursor, 0, (size_t)n * sizeof(int));
    k_hist<<<(et + TB - 1) / TB, TB>>>(ei, deg, ne, n);
    k_scan<<<1, 1024>>>(deg, rowptr, n);
    k_scatter<<<(et + TB - 1) / TB, TB>>>(ei, rowptr, cursor, esrc, ne, n);

    // ---- proj (fused embed-gather) -> x0 ----
    {
        dim3 g(1, (n + 127) / 128);
        k_gemm<true><<<g, TB>>>(nullptr, pW, pb, x0, n, 128, 192, 1, xp, emb);
    }

    // ---- layer 1 ----
    {
        dim3 g(4, (n + 127) / 128);
        k_gemm<false><<<g, TB>>>(x0, W1l, nullptr, xl1, n, 512, 128, 0, nullptr, nullptr);
        k_gemm<false><<<g, TB>>>(x0, W1r, nullptr, xr1, n, 512, 128, 0, nullptr, nullptr);
    }
    k_fused1<<<n, 128>>>(xl1, xr1, rowptr, esrc, att1, b1, agg1);

    // ---- layer 2 ----
    {
        dim3 g(1, (n + 127) / 128);
        k_gemm<false><<<g, TB>>>(agg1, W2l, nullptr, xl2, n, 128, 512, 0, nullptr, nullptr);
        k_gemm<false><<<g, TB>>>(agg1, W2r, nullptr, xr2, n, 128, 512, 0, nullptr, nullptr);
    }
    k_fused2<<<n, 128>>>(xl2, xr2, rowptr, esrc, att2, b2, agg2);

    // ---- output head ----
    k_out<<<(n * 10 + TB - 1) / TB, TB>>>(agg2, oW, ob, out, n);
}

// round 8
// speedup vs baseline: 1.6960x; 1.1102x over previous
#include <cuda_runtime.h>
#include <math.h>

// Problem constants (fixed shapes per reference)
#define NN   20000
#define EE   320000
#define ETOT (EE + NN)     // edges + self loops

// ---------------- scratch (device globals; no allocation allowed) ----------
__device__ float g_x0  [NN * 128];
__device__ float g_xl1 [NN * 512];
__device__ float g_xr1 [NN * 512];
__device__ float g_agg1[NN * 512];
__device__ float g_xl2 [NN * 128];
__device__ float g_xr2 [NN * 128];
// CSR scratch
__device__ int   g_deg   [NN + 1];
__device__ int   g_cursor[NN];
__device__ int   g_rowptr[NN + 1];
__device__ int   g_esrc  [ETOT];

// ---------------- GEMM: 128x128 tile, BK=16, double-buffered -----------------
// Computes C[M,N] = act(A @ B + bias). Grid.x covers nx tiles for (B1,C1) and,
// if B2 != null, nx more for (B2,C2) — merges the l/r weight GEMMs (shared A).
// GATHER builds A rows on the fly: cols 0..127 = emb[id[r]], cols 128.. = feats.
template <bool GATHER>
__global__ void __launch_bounds__(256)
k_gemm(const float* __restrict__ A,
       const float* __restrict__ B1, const float* __restrict__ B2,
       const float* __restrict__ bias,
       float* __restrict__ C1, float* __restrict__ C2,
       int M, int N, int K, int relu, int nx,
       const float* __restrict__ xp, const float* __restrict__ emb) {
    __shared__ float As[2][16][132];
    __shared__ float Bs[2][16][132];
    int tid = threadIdx.x;                 // 256 threads
    int tx = tid & 15, ty = tid >> 4;
    int bxr = blockIdx.x;
    bool sel = bxr >= nx;
    const float* B = sel ? B2 : B1;
    float* C = sel ? C2 : C1;
    int bn = (sel ? bxr - nx : bxr) * 128;
    int bm = blockIdx.y * 128;
    float acc[8][8] = {};

    int ar = tid >> 1;            // 0..127 : row within A tile
    int ac = (tid & 1) * 8;       // 0 or 8 : k offset (loads 8 floats)
    int br = tid >> 4;            // 0..15  : k row of B tile
    int bc = (tid & 15) * 8;      // col within B tile (loads 8 floats)
    bool aok = (bm + ar) < M;
    const float* Ap = GATHER ? nullptr : A + (size_t)(bm + ar) * K + ac;
    int gid = 0;
    if (GATHER && aok) gid = (int)xp[(size_t)(bm + ar) * 65];

    // gather-path A loader: logical column kc of row (bm+ar)
    auto gatherA4 = [&](int kc) -> float4 {
        if (!aok) return make_float4(0.f, 0.f, 0.f, 0.f);
        if (kc < 128) return *(const float4*)(emb + (size_t)gid * 128 + kc);
        const float* p = xp + (size_t)(bm + ar) * 65 + 1 + (kc - 128);
        return make_float4(p[0], p[1], p[2], p[3]);
    };

    int kiters = K >> 4;

    // prologue: stage tile 0
    float4 a0, a1, b0, b1;
    if (GATHER) {
        a0 = gatherA4(ac);
        a1 = gatherA4(ac + 4);
    } else {
        a0 = aok ? *(const float4*)(Ap)     : make_float4(0.f, 0.f, 0.f, 0.f);
        a1 = aok ? *(const float4*)(Ap + 4) : make_float4(0.f, 0.f, 0.f, 0.f);
    }
    b0 = *(const float4*)(B + (size_t)br * N + bn + bc);
    b1 = *(const float4*)(B + (size_t)br * N + bn + bc + 4);
    As[0][ac + 0][ar] = a0.x; As[0][ac + 1][ar] = a0.y;
    As[0][ac + 2][ar] = a0.z; As[0][ac + 3][ar] = a0.w;
    As[0][ac + 4][ar] = a1.x; As[0][ac + 5][ar] = a1.y;
    As[0][ac + 6][ar] = a1.z; As[0][ac + 7][ar] = a1.w;
    *(float4*)&Bs[0][br][bc]     = b0;
    *(float4*)&Bs[0][br][bc + 4] = b1;
    __syncthreads();

    int buf = 0;
    for (int it = 0; it < kiters; ++it) {
        bool have = (it + 1 < kiters);
        if (have) {
            int k0 = (it + 1) << 4;
            if (GATHER) {
                a0 = gatherA4(k0 + ac);
                a1 = gatherA4(k0 + ac + 4);
            } else {
                a0 = aok ? *(const float4*)(Ap + k0)     : make_float4(0.f, 0.f, 0.f, 0.f);
                a1 = aok ? *(const float4*)(Ap + k0 + 4) : make_float4(0.f, 0.f, 0.f, 0.f);
            }
            b0 = *(const float4*)(B + (size_t)(k0 + br) * N + bn + bc);
            b1 = *(const float4*)(B + (size_t)(k0 + br) * N + bn + bc + 4);
        }
#pragma unroll
        for (int kk = 0; kk < 16; kk++) {
            float a[8], b[8];
            *(float4*)(a)     = *(float4*)&As[buf][kk][ty * 4];
            *(float4*)(a + 4) = *(float4*)&As[buf][kk][64 + ty * 4];
            *(float4*)(b)     = *(float4*)&Bs[buf][kk][tx * 4];
            *(float4*)(b + 4) = *(float4*)&Bs[buf][kk][64 + tx * 4];
#pragma unroll
            for (int i = 0; i < 8; i++)
#pragma unroll
                for (int j = 0; j < 8; j++)
                    acc[i][j] += a[i] * b[j];
        }
        if (have) {
            int nb = buf ^ 1;
            As[nb][ac + 0][ar] = a0.x; As[nb][ac + 1][ar] = a0.y;
            As[nb][ac + 2][ar] = a0.z; As[nb][ac + 3][ar] = a0.w;
            As[nb][ac + 4][ar] = a1.x; As[nb][ac + 5][ar] = a1.y;
            As[nb][ac + 6][ar] = a1.z; As[nb][ac + 7][ar] = a1.w;
            *(float4*)&Bs[nb][br][bc]     = b0;
            *(float4*)&Bs[nb][br][bc + 4] = b1;
        }
        __syncthreads();
        buf ^= 1;
    }

#pragma unroll
    for (int hi = 0; hi < 2; hi++)
#pragma unroll
    for (int ii = 0; ii < 4; ii++) {
        int r = bm + hi * 64 + ty * 4 + ii;
        if (r >= M) continue;
#pragma unroll
        for (int hj = 0; hj < 2; hj++)
#pragma unroll
        for (int jj = 0; jj < 4; jj++) {
            int c = bn + hj * 64 + tx * 4 + jj;
            float v = acc[hi * 4 + ii][hj * 4 + jj];
            if (bias) v += bias[c];
            if (relu) v = fmaxf(v, 0.f);
            C[(size_t)r * N + c] = v;
        }
    }
}

// ---------------- CSR build --------------------------------------------------
__global__ void k_hist(const int* __restrict__ ei, int* __restrict__ deg, int ne, int nn) {
    int i = blockIdx.x * blockDim.x + threadIdx.x;
    int tot = ne + nn;
    if (i >= tot) return;
    int d = (i < ne) ? ei[ne + i] : i - ne;
    atomicAdd(&deg[d], 1);
}

// single-block warp-shuffle scan (1024 threads = 32 warps)
__global__ void k_scan(const int* __restrict__ deg, int* __restrict__ rowptr, int n) {
    __shared__ int wsum[32];
    __shared__ int carry_s;
    int t = threadIdx.x, lane = t & 31, wid = t >> 5;
    if (t == 0) carry_s = 0;
    __syncthreads();
    for (int base = 0; base < n; base += 1024) {
        int i = base + t;
        int carry = carry_s;
        int v = (i < n) ? deg[i] : 0;
        int x = v;
#pragma unroll
        for (int o = 1; o < 32; o <<= 1) {
            int y = __shfl_up_sync(0xffffffffu, x, o);
            if (lane >= o) x += y;
        }
        if (lane == 31) wsum[wid] = x;
        __syncthreads();
        if (wid == 0) {
            int s = wsum[lane];
#pragma unroll
            for (int o = 1; o < 32; o <<= 1) {
                int y = __shfl_up_sync(0xffffffffu, s, o);
                if (lane >= o) s += y;
            }
            wsum[lane] = s;
        }
        __syncthreads();
        int woff = wid ? wsum[wid - 1] : 0;
        if (i < n) rowptr[i] = carry + woff + x - v;   // exclusive
        int total = wsum[31];
        __syncthreads();
        if (t == 0) carry_s = carry + total;
        __syncthreads();
    }
    if (t == 0) rowptr[n] = carry_s;
}

__global__ void k_scatter(const int* __restrict__ ei, const int* __restrict__ rowptr,
                          int* __restrict__ cursor, int* __restrict__ esrc,
                          int ne, int nn) {
    int i = blockIdx.x * blockDim.x + threadIdx.x;
    int tot = ne + nn;
    if (i >= tot) return;
    int s, d;
    if (i < ne) { s = ei[i]; d = ei[ne + i]; } else { s = d = i - ne; }
    int pos = rowptr[d] + atomicAdd(&cursor[d], 1);
    esrc[pos] = s;
}

// ---------------- fused GATv2 edge phase (flash-style online softmax) --------
// Layer 1: 4 heads x 128 ch. Block = 128 threads (4 warps) per node.
__global__ void k_fused1(const float* __restrict__ xl, const float* __restrict__ xr,
                         const int* __restrict__ rowptr, const int* __restrict__ esrc,
                         const float* __restrict__ att, const float* __restrict__ bias,
                         float* __restrict__ out) {
    int node = blockIdx.x;
    int t = threadIdx.x, warp = t >> 5, lane = t & 31;
    int beg = rowptr[node], end = rowptr[node + 1];

    float xrv[16], attv[16];
    const float* pxr = xr + (size_t)node * 512;
#pragma unroll
    for (int i = 0; i < 16; i++) {
        int c = i * 32 + lane;
        xrv[i] = pxr[c];
        attv[i] = att[c];
    }
    float m[4] = {-INFINITY, -INFINITY, -INFINITY, -INFINITY};
    float s[4] = {0.f, 0.f, 0.f, 0.f};
    float acc[16] = {};

    for (int j = beg + warp; j < end; j += 4) {
        const float* px = xl + (size_t)esrc[j] * 512;
        float xv[16], p[4] = {0.f, 0.f, 0.f, 0.f};
#pragma unroll
        for (int i = 0; i < 16; i++) {
            xv[i] = px[i * 32 + lane];
            float v = xv[i] + xrv[i];
            v = v > 0.f ? v : 0.2f * v;
            p[i >> 2] += v * attv[i];
        }
#pragma unroll
        for (int o = 16; o; o >>= 1) {
            p[0] += __shfl_xor_sync(0xffffffffu, p[0], o);
            p[1] += __shfl_xor_sync(0xffffffffu, p[1], o);
            p[2] += __shfl_xor_sync(0xffffffffu, p[2], o);
            p[3] += __shfl_xor_sync(0xffffffffu, p[3], o);
        }
#pragma unroll
        for (int h = 0; h < 4; h++) {
            float e = p[h];
            float mn = fmaxf(m[h], e);
            float sc = __expf(m[h] - mn);       // first edge: exp(-inf)=0
            float w  = __expf(e - mn);
            s[h] = s[h] * sc + w;
            m[h] = mn;
#pragma unroll
            for (int i = 0; i < 4; i++) {
                int ii = h * 4 + i;
                acc[ii] = acc[ii] * sc + w * xv[ii];
            }
        }
    }

    __shared__ float sm[4][4], ss[4][4];
    __shared__ float sacc[4][512];
    if (lane < 4) { sm[warp][lane] = m[lane]; ss[warp][lane] = s[lane]; }
#pragma unroll
    for (int i = 0; i < 16; i++) sacc[warp][i * 32 + lane] = acc[i];
    __syncthreads();

#pragma unroll
    for (int h = 0; h < 4; h++) {
        int c = h * 128 + t;
        float M = fmaxf(fmaxf(sm[0][h], sm[1][h]), fmaxf(sm[2][h], sm[3][h]));
        float S = 0.f, A = 0.f;
#pragma unroll
        for (int w = 0; w < 4; w++) {
            float sc = __expf(sm[w][h] - M);    // empty warp: m=-inf -> 0
            S += ss[w][h] * sc;
            A += sacc[w][c] * sc;
        }
        out[(size_t)node * 512 + c] = fmaxf(A / (S + 1e-16f) + bias[c], 0.f);
    }
}

// Layer 2 (1 head x 128 ch) + fused output head: out[node,10].
__global__ void k_fused2(const float* __restrict__ xl, const float* __restrict__ xr,
                         const int* __restrict__ rowptr, const int* __restrict__ esrc,
                         const float* __restrict__ att, const float* __restrict__ bias,
                         const float* __restrict__ oW, const float* __restrict__ ob,
                         float* __restrict__ out) {
    int node = blockIdx.x;
    int t = threadIdx.x, warp = t >> 5, lane = t & 31;
    int beg = rowptr[node], end = rowptr[node + 1];

    float xrv[4], attv[4];
    const float* pxr = xr + (size_t)node * 128;
#pragma unroll
    for (int i = 0; i < 4; i++) {
        int c = i * 32 + lane;
        xrv[i] = pxr[c];
        attv[i] = att[c];
    }
    float m = -INFINITY, s = 0.f;
    float acc[4] = {};

    for (int j = beg + warp; j < end; j += 4) {
        const float* px = xl + (size_t)esrc[j] * 128;
        float xv[4], p = 0.f;
#pragma unroll
        for (int i = 0; i < 4; i++) {
            xv[i] = px[i * 32 + lane];
            float v = xv[i] + xrv[i];
            v = v > 0.f ? v : 0.2f * v;
            p += v * attv[i];
        }
#pragma unroll
        for (int o = 16; o; o >>= 1) p += __shfl_xor_sync(0xffffffffu, p, o);
        float mn = fmaxf(m, p);
        float sc = __expf(m - mn);
        float w  = __expf(p - mn);
        s = s * sc + w;
        m = mn;
#pragma unroll
        for (int i = 0; i < 4; i++) acc[i] = acc[i] * sc + w * xv[i];
    }

    __shared__ float sm[4], ss[4];
    __shared__ float sacc[4][128];
    if (!lane) { sm[warp] = m; ss[warp] = s; }
#pragma unroll
    for (int i = 0; i < 4; i++) sacc[warp][i * 32 + lane] = acc[i];
    __syncthreads();

    float M = fmaxf(fmaxf(sm[0], sm[1]), fmaxf(sm[2], sm[3]));
    float S = 0.f, A = 0.f;
#pragma unroll
    for (int w = 0; w < 4; w++) {
        float sc = __expf(sm[w] - M);
        S += ss[w] * sc;
        A += sacc[w][t] * sc;
    }
    float o_t = A / (S + 1e-16f) + bias[t];   // hidden value, channel t

    // fused output head: out[node,o] = sum_t o_t * oW[t,o] + ob[o]
    float p[10];
#pragma unroll
    for (int o = 0; o < 10; o++) p[o] = o_t * oW[t * 10 + o];
#pragma unroll
    for (int off = 16; off; off >>= 1)
#pragma unroll
        for (int o = 0; o < 10; o++) p[o] += __shfl_xor_sync(0xffffffffu, p[o], off);
    __shared__ float pp[4][10];
    if (!lane)
#pragma unroll
        for (int o = 0; o < 10; o++) pp[warp][o] = p[o];
    __syncthreads();
    if (t < 10) {
        float v = ob[t];
#pragma unroll
        for (int w = 0; w < 4; w++) v += pp[w][t];
        out[(size_t)node * 10 + t] = v;
    }
}

// ---------------- launch ----------------------------------------------------
extern "C" void kernel_launch(void* const* d_in, const int* in_sizes, int n_in,
                              void* d_out, int out_size) {
    const float* xp   = (const float*)d_in[0];
    const int*   ei   = (const int*)  d_in[1];
    const float* emb  = (const float*)d_in[2];
    const float* pW   = (const float*)d_in[3];
    const float* pb   = (const float*)d_in[4];
    const float* W1l  = (const float*)d_in[5];
    const float* W1r  = (const float*)d_in[6];
    const float* att1 = (const float*)d_in[7];
    const float* b1   = (const float*)d_in[8];
    const float* W2l  = (const float*)d_in[9];
    const float* W2r  = (const float*)d_in[10];
    const float* att2 = (const float*)d_in[11];
    const float* b2   = (const float*)d_in[12];
    const float* oW   = (const float*)d_in[13];
    const float* ob   = (const float*)d_in[14];
    float* out = (float*)d_out;

    int n  = in_sizes[0] / 65;
    int ne = in_sizes[1] / 2;
    int et = ne + n;

    float *x0, *xl1, *xr1, *agg1, *xl2, *xr2;
    int *deg, *cursor, *rowptr, *esrc;
    cudaGetSymbolAddress((void**)&x0,   g_x0);
    cudaGetSymbolAddress((void**)&xl1,  g_xl1);
    cudaGetSymbolAddress((void**)&xr1,  g_xr1);
    cudaGetSymbolAddress((void**)&agg1, g_agg1);
    cudaGetSymbolAddress((void**)&xl2,  g_xl2);
    cudaGetSymbolAddress((void**)&xr2,  g_xr2);
    cudaGetSymbolAddress((void**)&deg,    g_deg);
    cudaGetSymbolAddress((void**)&cursor, g_cursor);
    cudaGetSymbolAddress((void**)&rowptr, g_rowptr);
    cudaGetSymbolAddress((void**)&esrc,   g_esrc);

    const int TB = 256;
    int gm = (n + 127) / 128;

    // ---- CSR build ----
    cudaMemsetAsync(deg, 0, (size_t)(n + 1) * sizeof(int));
    cudaMemsetAsync(cursor, 0, (size_t)n * sizeof(int));
    k_hist<<<(et + TB - 1) / TB, TB>>>(ei, deg, ne, n);
    k_scan<<<1, 1024>>>(deg, rowptr, n);
    k_scatter<<<(et + TB - 1) / TB, TB>>>(ei, rowptr, cursor, esrc, ne, n);

    // ---- proj (fused embed-gather) -> x0 ----
    k_gemm<true><<<dim3(1, gm), TB>>>(nullptr, pW, nullptr, pb, x0, nullptr,
                                      n, 128, 192, 1, 1, xp, emb);

    // ---- layer 1: xl1 | xr1 in one launch ----
    k_gemm<false><<<dim3(8, gm), TB>>>(x0, W1l, W1r, nullptr, xl1, xr1,
                                       n, 512, 128, 0, 4, nullptr, nullptr);
    k_fused1<<<n, 128>>>(xl1, xr1, rowptr, esrc, att1, b1, agg1);

    // ---- layer 2: xl2 | xr2 in one launch ----
    k_gemm<false><<<dim3(2, gm), TB>>>(agg1, W2l, W2r, nullptr, xl2, xr2,
                                       n, 128, 512, 0, 1, nullptr, nullptr);
    k_fused2<<<n, 128>>>(xl2, xr2, rowptr, esrc, att2, b2, oW, ob, out);
}

// round 11
// speedup vs baseline: 1.7977x; 1.0600x over previous
#include <cuda_runtime.h>
#include <math.h>

// Problem constants (fixed shapes per reference)
#define NN   20000
#define EE   320000
#define ETOT (EE + NN)     // edges + self loops

// ---------------- scratch (device globals; no allocation allowed) ----------
__device__ float g_x0  [NN * 128];
__device__ float g_xl1 [NN * 512];
__device__ float g_xr1 [NN * 512];
__device__ float g_agg1[NN * 512];
__device__ float g_xl2 [NN * 128];
__device__ float g_xr2 [NN * 128];
// CSR scratch
__device__ int   g_deg   [NN + 1];
__device__ int   g_cursor[NN];
__device__ int   g_rowptr[NN + 1];
__device__ int   g_esrc  [ETOT];

// ---------------- tf32 helpers ----------------------------------------------
__device__ __forceinline__ unsigned f2tf(float x) {
    unsigned r;
    asm("cvt.rna.tf32.f32 %0, %1;" : "=r"(r) : "f"(x));
    return r;
}

__device__ __forceinline__ void mma_tf32(float* d, const unsigned* a, const unsigned* b) {
    asm volatile(
        "mma.sync.aligned.m16n8k8.row.col.f32.tf32.tf32.f32 "
        "{%0,%1,%2,%3}, {%4,%5,%6,%7}, {%8,%9}, {%0,%1,%2,%3};"
        : "+f"(d[0]), "+f"(d[1]), "+f"(d[2]), "+f"(d[3])
        : "r"(a[0]), "r"(a[1]), "r"(a[2]), "r"(a[3]), "r"(b[0]), "r"(b[1]));
}

// ---------------- GEMM: 128x128 tile, tensor-core 3xTF32 ---------------------
// C[M,N] = act(A @ B + bias). Grid.x covers nx tiles for (B1,C1) and, if
// B2 != null, nx more for (B2,C2) — merges the l/r weight GEMMs (shared A).
// GATHER builds A rows on the fly: cols 0..127 = emb[id[r]], cols 128.. = feats.
// Requires N % 128 == 0, K % 16 == 0.
template <bool GATHER>
__global__ void __launch_bounds__(256)
k_gemm(const float* __restrict__ A,
       const float* __restrict__ B1, const float* __restrict__ B2,
       const float* __restrict__ bias,
       float* __restrict__ C1, float* __restrict__ C2,
       int M, int N, int K, int relu, int nx,
       const float* __restrict__ xp, const float* __restrict__ emb) {
    // stride 136: 136 mod 32 = 8 -> k-columns map to disjoint bank octets
    __shared__ float Ah[16][136], Al[16][136];
    __shared__ float Bh[16][136], Bl[16][136];

    int tid  = threadIdx.x;                 // 256 threads = 8 warps
    int lane = tid & 31;
    int warp = tid >> 5;
    int wm = warp >> 2;                     // 0..1 : 64-row slab
    int wn = warp & 3;                      // 0..3 : 32-col slab
    int g  = lane >> 2;                     // group 0..7
    int tg = lane & 3;                      // thread-in-group 0..3

    int bxr = blockIdx.x;
    bool sel = bxr >= nx;
    const float* B = sel ? B2 : B1;
    float* C = sel ? C2 : C1;
    int bn = (sel ? bxr - nx : bxr) * 128;
    int bm = blockIdx.y * 128;

    float acc[4][4][4] = {};                // [mt][nt][c0..c3]

    // global staging roles
    int ar = tid >> 1;                      // 0..127 : A-tile row
    int ac = (tid & 1) * 8;                 // 0 or 8 : A k-offset (8 floats)
    int br = tid >> 4;                      // 0..15  : B k-row
    int bc = (tid & 15) * 8;                // B col offset (8 floats)
    bool aok = (bm + ar) < M;
    const float* Ap = GATHER ? nullptr : A + (size_t)(bm + ar) * K + ac;
    int gid = 0;
    if (GATHER && aok) gid = (int)xp[(size_t)(bm + ar) * 65];

    for (int k0 = 0; k0 < K; k0 += 16) {
        // ---- stage global loads ----
        float av[8], bv[8];
        if (aok) {
            if (GATHER) {
#pragma unroll
                for (int h = 0; h < 2; h++) {
                    int kc = k0 + ac + h * 4;
                    float4 v;
                    if (kc < 128) {
                        v = *(const float4*)(emb + (size_t)gid * 128 + kc);
                    } else {
                        const float* p = xp + (size_t)(bm + ar) * 65 + 1 + (kc - 128);
                        v = make_float4(p[0], p[1], p[2], p[3]);
                    }
                    av[h * 4 + 0] = v.x; av[h * 4 + 1] = v.y;
                    av[h * 4 + 2] = v.z; av[h * 4 + 3] = v.w;
                }
            } else {
                float4 v0 = *(const float4*)(Ap + k0);
                float4 v1 = *(const float4*)(Ap + k0 + 4);
                av[0] = v0.x; av[1] = v0.y; av[2] = v0.z; av[3] = v0.w;
                av[4] = v1.x; av[5] = v1.y; av[6] = v1.z; av[7] = v1.w;
            }
        } else {
#pragma unroll
            for (int i = 0; i < 8; i++) av[i] = 0.f;
        }
        {
            float4 v0 = *(const float4*)(B + (size_t)(k0 + br) * N + bn + bc);
            float4 v1 = *(const float4*)(B + (size_t)(k0 + br) * N + bn + bc + 4);
            bv[0] = v0.x; bv[1] = v0.y; bv[2] = v0.z; bv[3] = v0.w;
            bv[4] = v1.x; bv[5] = v1.y; bv[6] = v1.z; bv[7] = v1.w;
        }

        if (k0 > 0) __syncthreads();        // previous tile's compute done

        // ---- split hi/lo (tf32-rounded) and store to smem ----
#pragma unroll
        for (int i = 0; i < 8; i++) {
            float hi = __uint_as_float(f2tf(av[i]));
            float lo = __uint_as_float(f2tf(av[i] - hi));
            Ah[ac + i][ar] = hi;
            Al[ac + i][ar] = lo;
        }
#pragma unroll
        for (int i = 0; i < 8; i++) {
            float hi = __uint_as_float(f2tf(bv[i]));
            float lo = __uint_as_float(f2tf(bv[i] - hi));
            Bh[br][bc + i] = hi;
            Bl[br][bc + i] = lo;
        }
        __syncthreads();

        // ---- compute: two k-chunks of 8 ----
#pragma unroll
        for (int kc = 0; kc < 16; kc += 8) {
            // B fragments for the 4 n-tiles (hi & lo)
            unsigned bhf[4][2], blf[4][2];
#pragma unroll
            for (int nt = 0; nt < 4; nt++) {
                int col = wn * 32 + nt * 8 + g;
                bhf[nt][0] = __float_as_uint(Bh[kc + tg][col]);
                bhf[nt][1] = __float_as_uint(Bh[kc + tg + 4][col]);
                blf[nt][0] = __float_as_uint(Bl[kc + tg][col]);
                blf[nt][1] = __float_as_uint(Bl[kc + tg + 4][col]);
            }
#pragma unroll
            for (int mt = 0; mt < 4; mt++) {
                int row = wm * 64 + mt * 16 + g;
                unsigned ahf[4], alf[4];
                ahf[0] = __float_as_uint(Ah[kc + tg][row]);
                ahf[1] = __float_as_uint(Ah[kc + tg][row + 8]);
                ahf[2] = __float_as_uint(Ah[kc + tg + 4][row]);
                ahf[3] = __float_as_uint(Ah[kc + tg + 4][row + 8]);
                alf[0] = __float_as_uint(Al[kc + tg][row]);
                alf[1] = __float_as_uint(Al[kc + tg][row + 8]);
                alf[2] = __float_as_uint(Al[kc + tg + 4][row]);
                alf[3] = __float_as_uint(Al[kc + tg + 4][row + 8]);
#pragma unroll
                for (int nt = 0; nt < 4; nt++) {
                    mma_tf32(acc[mt][nt], ahf, bhf[nt]);   // hi*hi
                    mma_tf32(acc[mt][nt], ahf, blf[nt]);   // hi*lo
                    mma_tf32(acc[mt][nt], alf, bhf[nt]);   // lo*hi
                }
            }
        }
    }

    // ---- epilogue ----
#pragma unroll
    for (int mt = 0; mt < 4; mt++) {
        int r0 = bm + wm * 64 + mt * 16 + g;
#pragma unroll
        for (int nt = 0; nt < 4; nt++) {
            int c0 = bn + wn * 32 + nt * 8 + tg * 2;
            float v0 = acc[mt][nt][0], v1 = acc[mt][nt][1];
            float v2 = acc[mt][nt][2], v3 = acc[mt][nt][3];
            if (bias) {
                v0 += bias[c0]; v1 += bias[c0 + 1];
                v2 += bias[c0]; v3 += bias[c0 + 1];
            }
            if (relu) {
                v0 = fmaxf(v0, 0.f); v1 = fmaxf(v1, 0.f);
                v2 = fmaxf(v2, 0.f); v3 = fmaxf(v3, 0.f);
            }
            if (r0 < M)     *(float2*)(C + (size_t)r0 * N + c0)       = make_float2(v0, v1);
            if (r0 + 8 < M) *(float2*)(C + (size_t)(r0 + 8) * N + c0) = make_float2(v2, v3);
        }
    }
}

// ---------------- CSR build --------------------------------------------------
__global__ void k_hist(const int* __restrict__ ei, int* __restrict__ deg, int ne, int nn) {
    int i = blockIdx.x * blockDim.x + threadIdx.x;
    int tot = ne + nn;
    if (i >= tot) return;
    int d = (i < ne) ? ei[ne + i] : i - ne;
    atomicAdd(&deg[d], 1);
}

// single-block warp-shuffle scan (1024 threads = 32 warps)
__global__ void k_scan(const int* __restrict__ deg, int* __restrict__ rowptr, int n) {
    __shared__ int wsum[32];
    __shared__ int carry_s;
    int t = threadIdx.x, lane = t & 31, wid = t >> 5;
    if (t == 0) carry_s = 0;
    __syncthreads();
    for (int base = 0; base < n; base += 1024) {
        int i = base + t;
        int carry = carry_s;
        int v = (i < n) ? deg[i] : 0;
        int x = v;
#pragma unroll
        for (int o = 1; o < 32; o <<= 1) {
            int y = __shfl_up_sync(0xffffffffu, x, o);
            if (lane >= o) x += y;
        }
        if (lane == 31) wsum[wid] = x;
        __syncthreads();
        if (wid == 0) {
            int s = wsum[lane];
#pragma unroll
            for (int o = 1; o < 32; o <<= 1) {
                int y = __shfl_up_sync(0xffffffffu, s, o);
                if (lane >= o) s += y;
            }
            wsum[lane] = s;
        }
        __syncthreads();
        int woff = wid ? wsum[wid - 1] : 0;
        if (i < n) rowptr[i] = carry + woff + x - v;   // exclusive
        int total = wsum[31];
        __syncthreads();
        if (t == 0) carry_s = carry + total;
        __syncthreads();
    }
    if (t == 0) rowptr[n] = carry_s;
}

__global__ void k_scatter(const int* __restrict__ ei, const int* __restrict__ rowptr,
                          int* __restrict__ cursor, int* __restrict__ esrc,
                          int ne, int nn) {
    int i = blockIdx.x * blockDim.x + threadIdx.x;
    int tot = ne + nn;
    if (i >= tot) return;
    int s, d;
    if (i < ne) { s = ei[i]; d = ei[ne + i]; } else { s = d = i - ne; }
    int pos = rowptr[d] + atomicAdd(&cursor[d], 1);
    esrc[pos] = s;
}

// ---------------- fused GATv2 edge phase (flash-style online softmax) --------
// Layer 1: 4 heads x 128 ch. Block = 128 threads (4 warps) per node.
__global__ void k_fused1(const float* __restrict__ xl, const float* __restrict__ xr,
                         const int* __restrict__ rowptr, const int* __restrict__ esrc,
                         const float* __restrict__ att, const float* __restrict__ bias,
                         float* __restrict__ out) {
    int node = blockIdx.x;
    int t = threadIdx.x, warp = t >> 5, lane = t & 31;
    int beg = rowptr[node], end = rowptr[node + 1];

    float xrv[16], attv[16];
    const float* pxr = xr + (size_t)node * 512;
#pragma unroll
    for (int i = 0; i < 16; i++) {
        int c = i * 32 + lane;
        xrv[i] = pxr[c];
        attv[i] = att[c];
    }
    float m[4] = {-INFINITY, -INFINITY, -INFINITY, -INFINITY};
    float s[4] = {0.f, 0.f, 0.f, 0.f};
    float acc[16] = {};

    for (int j = beg + warp; j < end; j += 4) {
        const float* px = xl + (size_t)esrc[j] * 512;
        float xv[16], p[4] = {0.f, 0.f, 0.f, 0.f};
#pragma unroll
        for (int i = 0; i < 16; i++) {
            xv[i] = px[i * 32 + lane];
            float v = xv[i] + xrv[i];
            v = v > 0.f ? v : 0.2f * v;
            p[i >> 2] += v * attv[i];
        }
#pragma unroll
        for (int o = 16; o; o >>= 1) {
            p[0] += __shfl_xor_sync(0xffffffffu, p[0], o);
            p[1] += __shfl_xor_sync(0xffffffffu, p[1], o);
            p[2] += __shfl_xor_sync(0xffffffffu, p[2], o);
            p[3] += __shfl_xor_sync(0xffffffffu, p[3], o);
        }
#pragma unroll
        for (int h = 0; h < 4; h++) {
            float e = p[h];
            float mn = fmaxf(m[h], e);
            float sc = __expf(m[h] - mn);       // first edge: exp(-inf)=0
            float w  = __expf(e - mn);
            s[h] = s[h] * sc + w;
            m[h] = mn;
#pragma unroll
            for (int i = 0; i < 4; i++) {
                int ii = h * 4 + i;
                acc[ii] = acc[ii] * sc + w * xv[ii];
            }
        }
    }

    __shared__ float sm[4][4], ss[4][4];
    __shared__ float sacc[4][512];
    if (lane < 4) { sm[warp][lane] = m[lane]; ss[warp][lane] = s[lane]; }
#pragma unroll
    for (int i = 0; i < 16; i++) sacc[warp][i * 32 + lane] = acc[i];
    __syncthreads();

#pragma unroll
    for (int h = 0; h < 4; h++) {
        int c = h * 128 + t;
        float M = fmaxf(fmaxf(sm[0][h], sm[1][h]), fmaxf(sm[2][h], sm[3][h]));
        float S = 0.f, A = 0.f;
#pragma unroll
        for (int w = 0; w < 4; w++) {
            float sc = __expf(sm[w][h] - M);    // empty warp: m=-inf -> 0
            S += ss[w][h] * sc;
            A += sacc[w][c] * sc;
        }
        out[(size_t)node * 512 + c] = fmaxf(A / (S + 1e-16f) + bias[c], 0.f);
    }
}

// Layer 2 (1 head x 128 ch) + fused output head: out[node,10].
__global__ void k_fused2(const float* __restrict__ xl, const float* __restrict__ xr,
                         const int* __restrict__ rowptr, const int* __restrict__ esrc,
                         const float* __restrict__ att, const float* __restrict__ bias,
                         const float* __restrict__ oW, const float* __restrict__ ob,
                         float* __restrict__ out) {
    int node = blockIdx.x;
    int t = threadIdx.x, warp = t >> 5, lane = t & 31;
    int beg = rowptr[node], end = rowptr[node + 1];

    float xrv[4], attv[4];
    const float* pxr = xr + (size_t)node * 128;
#pragma unroll
    for (int i = 0; i < 4; i++) {
        int c = i * 32 + lane;
        xrv[i] = pxr[c];
        attv[i] = att[c];
    }
    float m = -INFINITY, s = 0.f;
    float acc[4] = {};

    for (int j = beg + warp; j < end; j += 4) {
        const float* px = xl + (size_t)esrc[j] * 128;
        float xv[4], p = 0.f;
#pragma unroll
        for (int i = 0; i < 4; i++) {
            xv[i] = px[i * 32 + lane];
            float v = xv[i] + xrv[i];
            v = v > 0.f ? v : 0.2f * v;
            p += v * attv[i];
        }
#pragma unroll
        for (int o = 16; o; o >>= 1) p += __shfl_xor_sync(0xffffffffu, p, o);
        float mn = fmaxf(m, p);
        float sc = __expf(m - mn);
        float w  = __expf(p - mn);
        s = s * sc + w;
        m = mn;
#pragma unroll
        for (int i = 0; i < 4; i++) acc[i] = acc[i] * sc + w * xv[i];
    }

    __shared__ float sm[4], ss[4];
    __shared__ float sacc[4][128];
    if (!lane) { sm[warp] = m; ss[warp] = s; }
#pragma unroll
    for (int i = 0; i < 4; i++) sacc[warp][i * 32 + lane] = acc[i];
    __syncthreads();

    float M = fmaxf(fmaxf(sm[0], sm[1]), fmaxf(sm[2], sm[3]));
    float S = 0.f, A = 0.f;
#pragma unroll
    for (int w = 0; w < 4; w++) {
        float sc = __expf(sm[w] - M);
        S += ss[w] * sc;
        A += sacc[w][t] * sc;
    }
    float o_t = A / (S + 1e-16f) + bias[t];   // hidden value, channel t

    // fused output head: out[node,o] = sum_t o_t * oW[t,o] + ob[o]
    float p[10];
#pragma unroll
    for (int o = 0; o < 10; o++) p[o] = o_t * oW[t * 10 + o];
#pragma unroll
    for (int off = 16; off; off >>= 1)
#pragma unroll
        for (int o = 0; o < 10; o++) p[o] += __shfl_xor_sync(0xffffffffu, p[o], off);
    __shared__ float pp[4][10];
    if (!lane)
#pragma unroll
        for (int o = 0; o < 10; o++) pp[warp][o] = p[o];
    __syncthreads();
    if (t < 10) {
        float v = ob[t];
#pragma unroll
        for (int w = 0; w < 4; w++) v += pp[w][t];
        out[(size_t)node * 10 + t] = v;
    }
}

// ---------------- launch ----------------------------------------------------
extern "C" void kernel_launch(void* const* d_in, const int* in_sizes, int n_in,
                              void* d_out, int out_size) {
    const float* xp   = (const float*)d_in[0];
    const int*   ei   = (const int*)  d_in[1];
    const float* emb  = (const float*)d_in[2];
    const float* pW   = (const float*)d_in[3];
    const float* pb   = (const float*)d_in[4];
    const float* W1l  = (const float*)d_in[5];
    const float* W1r  = (const float*)d_in[6];
    const float* att1 = (const float*)d_in[7];
    const float* b1   = (const float*)d_in[8];
    const float* W2l  = (const float*)d_in[9];
    const float* W2r  = (const float*)d_in[10];
    const float* att2 = (const float*)d_in[11];
    const float* b2   = (const float*)d_in[12];
    const float* oW   = (const float*)d_in[13];
    const float* ob   = (const float*)d_in[14];
    float* out = (float*)d_out;

    int n  = in_sizes[0] / 65;
    int ne = in_sizes[1] / 2;
    int et = ne + n;

    float *x0, *xl1, *xr1, *agg1, *xl2, *xr2;
    int *deg, *cursor, *rowptr, *esrc;
    cudaGetSymbolAddress((void**)&x0,   g_x0);
    cudaGetSymbolAddress((void**)&xl1,  g_xl1);
    cudaGetSymbolAddress((void**)&xr1,  g_xr1);
    cudaGetSymbolAddress((void**)&agg1, g_agg1);
    cudaGetSymbolAddress((void**)&xl2,  g_xl2);
    cudaGetSymbolAddress((void**)&xr2,  g_xr2);
    cudaGetSymbolAddress((void**)&deg,    g_deg);
    cudaGetSymbolAddress((void**)&cursor, g_cursor);
    cudaGetSymbolAddress((void**)&rowptr, g_rowptr);
    cudaGetSymbolAddress((void**)&esrc,   g_esrc);

    const int TB = 256;
    int gm = (n + 127) / 128;

    // ---- CSR build ----
    cudaMemsetAsync(deg, 0, (size_t)(n + 1) * sizeof(int));
    cudaMemsetAsync(cursor, 0, (size_t)n * sizeof(int));
    k_hist<<<(et + TB - 1) / TB, TB>>>(ei, deg, ne, n);
    k_scan<<<1, 1024>>>(deg, rowptr, n);
    k_scatter<<<(et + TB - 1) / TB, TB>>>(ei, rowptr, cursor, esrc, ne, n);

    // ---- proj (fused embed-gather) -> x0 ----
    k_gemm<true><<<dim3(1, gm), TB>>>(nullptr, pW, nullptr, pb, x0, nullptr,
                                      n, 128, 192, 1, 1, xp, emb);

    // ---- layer 1: xl1 | xr1 in one launch ----
    k_gemm<false><<<dim3(8, gm), TB>>>(x0, W1l, W1r, nullptr, xl1, xr1,
                                       n, 512, 128, 0, 4, nullptr, nullptr);
    k_fused1<<<n, 128>>>(xl1, xr1, rowptr, esrc, att1, b1, agg1);

    // ---- layer 2: xl2 | xr2 in one launch ----
    k_gemm<false><<<dim3(2, gm), TB>>>(agg1, W2l, W2r, nullptr, xl2, xr2,
                                       n, 128, 512, 0, 1, nullptr, nullptr);
    k_fused2<<<n, 128>>>(xl2, xr2, rowptr, esrc, att2, b2, oW, ob, out);
}

// round 12
// speedup vs baseline: 2.0199x; 1.1236x over previous
#include <cuda_runtime.h>
#include <math.h>

// Problem constants (fixed shapes per reference)
#define NN   20000
#define EE   320000
#define ETOT (EE + NN)     // edges + self loops

// ---------------- scratch (device globals; no allocation allowed) ----------
__device__ float g_x0  [NN * 128];
__device__ float g_xl1 [NN * 512];
__device__ float g_xr1 [NN * 512];
__device__ float g_agg1[NN * 512];
__device__ float g_xl2 [NN * 128];
__device__ float g_xr2 [NN * 128];
// CSR scratch
__device__ int   g_deg   [NN + 1];
__device__ int   g_cursor[NN];
__device__ int   g_rowptr[NN + 1];
__device__ int   g_esrc  [ETOT];

// ---------------- tf32 helpers ----------------------------------------------
__device__ __forceinline__ unsigned f2tf(float x) {
    unsigned r;
    asm("cvt.rna.tf32.f32 %0, %1;" : "=r"(r) : "f"(x));
    return r;
}

__device__ __forceinline__ void mma_tf32(float* d, const unsigned* a, const unsigned* b) {
    asm volatile(
        "mma.sync.aligned.m16n8k8.row.col.f32.tf32.tf32.f32 "
        "{%0,%1,%2,%3}, {%4,%5,%6,%7}, {%8,%9}, {%0,%1,%2,%3};"
        : "+f"(d[0]), "+f"(d[1]), "+f"(d[2]), "+f"(d[3])
        : "r"(a[0]), "r"(a[1]), "r"(a[2]), "r"(a[3]), "r"(b[0]), "r"(b[1]));
}

// ---------------- GEMM: 64x128 tile, 3xTF32, double-buffered -----------------
// C[M,N] = act(A @ B + bias). Grid.x covers nx tiles for (B1,C1) and, if
// B2 != null, nx more for (B2,C2) — merges the l/r weight GEMMs (shared A).
// GATHER builds A rows on the fly: cols 0..127 = emb[id[r]], cols 128.. = feats.
// Requires N % 128 == 0, K % 16 == 0. Dynamic smem = 53248 bytes.
#define GEMM_SMEM 53248
template <bool GATHER>
__global__ void __launch_bounds__(256, 2)
k_gemm(const float* __restrict__ A,
       const float* __restrict__ B1, const float* __restrict__ B2,
       const float* __restrict__ bias,
       float* __restrict__ C1, float* __restrict__ C2,
       int M, int N, int K, int relu, int nx,
       const float* __restrict__ xp, const float* __restrict__ emb) {
    extern __shared__ float sm[];
    // per buffer: Ah[16][72] Al[16][72] Bh[16][136] Bl[16][136]
    const int ASTR = 72, BSTR = 136;
    const int ASZ = 16 * ASTR;              // 1152
    const int BSZ = 16 * BSTR;              // 2176
    const int BUFSZ = 2 * ASZ + 2 * BSZ;    // 6656 floats

    int tid  = threadIdx.x;                 // 256 threads = 8 warps
    int lane = tid & 31;
    int warp = tid >> 5;
    int wm = warp >> 2;                     // 0..1 : 32-row slab
    int wn = warp & 3;                      // 0..3 : 32-col slab
    int g  = lane >> 2;                     // group 0..7
    int tg = lane & 3;                      // thread-in-group 0..3

    int bxr = blockIdx.x;
    bool sel = bxr >= nx;
    const float* B = sel ? B2 : B1;
    float* C = sel ? C2 : C1;
    int bn = (sel ? bxr - nx : bxr) * 128;
    int bm = blockIdx.y * 64;

    float acc[2][4][4] = {};                // [mt][nt][c0..c3]

    // global staging roles
    int ar = tid >> 2;                      // 0..63 : A-tile row
    int ac = (tid & 3) * 4;                 // 0,4,8,12 : A k-offset (4 floats)
    int br = tid >> 4;                      // 0..15  : B k-row
    int bc = (tid & 15) * 8;                // B col offset (8 floats)
    bool aok = (bm + ar) < M;
    const float* Ap = GATHER ? nullptr : A + (size_t)(bm + ar) * K + ac;
    int gid = 0;
    if (GATHER && aok) gid = (int)xp[(size_t)(bm + ar) * 65];

    float av[4], bv[8];
    auto loadTile = [&](int k0) {
        if (aok) {
            if (GATHER) {
                int kc = k0 + ac;
                if (kc < 128) {
                    float4 v = *(const float4*)(emb + (size_t)gid * 128 + kc);
                    av[0] = v.x; av[1] = v.y; av[2] = v.z; av[3] = v.w;
                } else {
                    const float* p = xp + (size_t)(bm + ar) * 65 + 1 + (kc - 128);
                    av[0] = p[0]; av[1] = p[1]; av[2] = p[2]; av[3] = p[3];
                }
            } else {
                float4 v = *(const float4*)(Ap + k0);
                av[0] = v.x; av[1] = v.y; av[2] = v.z; av[3] = v.w;
            }
        } else {
            av[0] = av[1] = av[2] = av[3] = 0.f;
        }
        float4 v0 = *(const float4*)(B + (size_t)(k0 + br) * N + bn + bc);
        float4 v1 = *(const float4*)(B + (size_t)(k0 + br) * N + bn + bc + 4);
        bv[0] = v0.x; bv[1] = v0.y; bv[2] = v0.z; bv[3] = v0.w;
        bv[4] = v1.x; bv[5] = v1.y; bv[6] = v1.z; bv[7] = v1.w;
    };

    auto stage = [&](int buf) {
        float* Ah = sm + buf * BUFSZ;
        float* Al = Ah + ASZ;
        float* Bh = sm + buf * BUFSZ + 2 * ASZ;
        float* Bl = Bh + BSZ;
#pragma unroll
        for (int i = 0; i < 4; i++) {
            float hi = __uint_as_float(f2tf(av[i]));
            float lo = __uint_as_float(f2tf(av[i] - hi));
            Ah[(ac + i) * ASTR + ar] = hi;
            Al[(ac + i) * ASTR + ar] = lo;
        }
#pragma unroll
        for (int i = 0; i < 8; i++) {
            float hi = __uint_as_float(f2tf(bv[i]));
            float lo = __uint_as_float(f2tf(bv[i] - hi));
            Bh[br * BSTR + bc + i] = hi;
            Bl[br * BSTR + bc + i] = lo;
        }
    };

    auto compute = [&](int buf) {
        const float* Ah = sm + buf * BUFSZ;
        const float* Al = Ah + ASZ;
        const float* Bh = sm + buf * BUFSZ + 2 * ASZ;
        const float* Bl = Bh + BSZ;
#pragma unroll
        for (int kc = 0; kc < 16; kc += 8) {
            unsigned bhf[4][2], blf[4][2];
#pragma unroll
            for (int nt = 0; nt < 4; nt++) {
                int col = wn * 32 + nt * 8 + g;
                bhf[nt][0] = __float_as_uint(Bh[(kc + tg) * BSTR + col]);
                bhf[nt][1] = __float_as_uint(Bh[(kc + tg + 4) * BSTR + col]);
                blf[nt][0] = __float_as_uint(Bl[(kc + tg) * BSTR + col]);
                blf[nt][1] = __float_as_uint(Bl[(kc + tg + 4) * BSTR + col]);
            }
#pragma unroll
            for (int mt = 0; mt < 2; mt++) {
                int row = wm * 32 + mt * 16 + g;
                unsigned ahf[4], alf[4];
                ahf[0] = __float_as_uint(Ah[(kc + tg) * ASTR + row]);
                ahf[1] = __float_as_uint(Ah[(kc + tg) * ASTR + row + 8]);
                ahf[2] = __float_as_uint(Ah[(kc + tg + 4) * ASTR + row]);
                ahf[3] = __float_as_uint(Ah[(kc + tg + 4) * ASTR + row + 8]);
                alf[0] = __float_as_uint(Al[(kc + tg) * ASTR + row]);
                alf[1] = __float_as_uint(Al[(kc + tg) * ASTR + row + 8]);
                alf[2] = __float_as_uint(Al[(kc + tg + 4) * ASTR + row]);
                alf[3] = __float_as_uint(Al[(kc + tg + 4) * ASTR + row + 8]);
#pragma unroll
                for (int nt = 0; nt < 4; nt++) {
                    mma_tf32(acc[mt][nt], ahf, bhf[nt]);   // hi*hi
                    mma_tf32(acc[mt][nt], ahf, blf[nt]);   // hi*lo
                    mma_tf32(acc[mt][nt], alf, bhf[nt]);   // lo*hi
                }
            }
        }
    };

    int kiters = K >> 4;
    loadTile(0);
    stage(0);
    __syncthreads();
    for (int it = 0; it < kiters; ++it) {
        int buf = it & 1;
        bool have = (it + 1 < kiters);
        if (have) loadTile((it + 1) << 4);
        compute(buf);
        if (have) stage(buf ^ 1);
        __syncthreads();
    }

    // ---- epilogue ----
#pragma unroll
    for (int mt = 0; mt < 2; mt++) {
        int r0 = bm + wm * 32 + mt * 16 + g;
#pragma unroll
        for (int nt = 0; nt < 4; nt++) {
            int c0 = bn + wn * 32 + nt * 8 + tg * 2;
            float v0 = acc[mt][nt][0], v1 = acc[mt][nt][1];
            float v2 = acc[mt][nt][2], v3 = acc[mt][nt][3];
            if (bias) {
                v0 += bias[c0]; v1 += bias[c0 + 1];
                v2 += bias[c0]; v3 += bias[c0 + 1];
            }
            if (relu) {
                v0 = fmaxf(v0, 0.f); v1 = fmaxf(v1, 0.f);
                v2 = fmaxf(v2, 0.f); v3 = fmaxf(v3, 0.f);
            }
            if (r0 < M)     *(float2*)(C + (size_t)r0 * N + c0)       = make_float2(v0, v1);
            if (r0 + 8 < M) *(float2*)(C + (size_t)(r0 + 8) * N + c0) = make_float2(v2, v3);
        }
    }
}

// ---------------- CSR build --------------------------------------------------
__global__ void k_hist(const int* __restrict__ ei, int* __restrict__ deg, int ne, int nn) {
    int i = blockIdx.x * blockDim.x + threadIdx.x;
    int tot = ne + nn;
    if (i >= tot) return;
    int d = (i < ne) ? ei[ne + i] : i - ne;
    atomicAdd(&deg[d], 1);
}

// single-block warp-shuffle scan (1024 threads = 32 warps)
__global__ void k_scan(const int* __restrict__ deg, int* __restrict__ rowptr, int n) {
    __shared__ int wsum[32];
    __shared__ int carry_s;
    int t = threadIdx.x, lane = t & 31, wid = t >> 5;
    if (t == 0) carry_s = 0;
    __syncthreads();
    for (int base = 0; base < n; base += 1024) {
        int i = base + t;
        int carry = carry_s;
        int v = (i < n) ? deg[i] : 0;
        int x = v;
#pragma unroll
        for (int o = 1; o < 32; o <<= 1) {
            int y = __shfl_up_sync(0xffffffffu, x, o);
            if (lane >= o) x += y;
        }
        if (lane == 31) wsum[wid] = x;
        __syncthreads();
        if (wid == 0) {
            int s = wsum[lane];
#pragma unroll
            for (int o = 1; o < 32; o <<= 1) {
                int y = __shfl_up_sync(0xffffffffu, s, o);
                if (lane >= o) s += y;
            }
            wsum[lane] = s;
        }
        __syncthreads();
        int woff = wid ? wsum[wid - 1] : 0;
        if (i < n) rowptr[i] = carry + woff + x - v;   // exclusive
        int total = wsum[31];
        __syncthreads();
        if (t == 0) carry_s = carry + total;
        __syncthreads();
    }
    if (t == 0) rowptr[n] = carry_s;
}

__global__ void k_scatter(const int* __restrict__ ei, const int* __restrict__ rowptr,
                          int* __restrict__ cursor, int* __restrict__ esrc,
                          int ne, int nn) {
    int i = blockIdx.x * blockDim.x + threadIdx.x;
    int tot = ne + nn;
    if (i >= tot) return;
    int s, d;
    if (i < ne) { s = ei[i]; d = ei[ne + i]; } else { s = d = i - ne; }
    int pos = rowptr[d] + atomicAdd(&cursor[d], 1);
    esrc[pos] = s;
}

// ---------------- fused GATv2 edge phase (flash-style online softmax) --------
// Layer 1: 4 heads x 128 ch. Block = 128 threads (4 warps) per node.
__global__ void k_fused1(const float* __restrict__ xl, const float* __restrict__ xr,
                         const int* __restrict__ rowptr, const int* __restrict__ esrc,
                         const float* __restrict__ att, const float* __restrict__ bias,
                         float* __restrict__ out) {
    int node = blockIdx.x;
    int t = threadIdx.x, warp = t >> 5, lane = t & 31;
    int beg = rowptr[node], end = rowptr[node + 1];

    float xrv[16], attv[16];
    const float* pxr = xr + (size_t)node * 512;
#pragma unroll
    for (int i = 0; i < 16; i++) {
        int c = i * 32 + lane;
        xrv[i] = pxr[c];
        attv[i] = att[c];
    }
    float m[4] = {-INFINITY, -INFINITY, -INFINITY, -INFINITY};
    float s[4] = {0.f, 0.f, 0.f, 0.f};
    float acc[16] = {};

    for (int j = beg + warp; j < end; j += 4) {
        const float* px = xl + (size_t)esrc[j] * 512;
        float xv[16], p[4] = {0.f, 0.f, 0.f, 0.f};
#pragma unroll
        for (int i = 0; i < 16; i++) {
            xv[i] = px[i * 32 + lane];
            float v = xv[i] + xrv[i];
            v = v > 0.f ? v : 0.2f * v;
            p[i >> 2] += v * attv[i];
        }
#pragma unroll
        for (int o = 16; o; o >>= 1) {
            p[0] += __shfl_xor_sync(0xffffffffu, p[0], o);
            p[1] += __shfl_xor_sync(0xffffffffu, p[1], o);
            p[2] += __shfl_xor_sync(0xffffffffu, p[2], o);
            p[3] += __shfl_xor_sync(0xffffffffu, p[3], o);
        }
#pragma unroll
        for (int h = 0; h < 4; h++) {
            float e = p[h];
            float mn = fmaxf(m[h], e);
            float sc = __expf(m[h] - mn);       // first edge: exp(-inf)=0
            float w  = __expf(e - mn);
            s[h] = s[h] * sc + w;
            m[h] = mn;
#pragma unroll
            for (int i = 0; i < 4; i++) {
                int ii = h * 4 + i;
                acc[ii] = acc[ii] * sc + w * xv[ii];
            }
        }
    }

    __shared__ float sm[4][4], ss[4][4];
    __shared__ float sacc[4][512];
    if (lane < 4) { sm[warp][lane] = m[lane]; ss[warp][lane] = s[lane]; }
#pragma unroll
    for (int i = 0; i < 16; i++) sacc[warp][i * 32 + lane] = acc[i];
    __syncthreads();

#pragma unroll
    for (int h = 0; h < 4; h++) {
        int c = h * 128 + t;
        float M = fmaxf(fmaxf(sm[0][h], sm[1][h]), fmaxf(sm[2][h], sm[3][h]));
        float S = 0.f, A = 0.f;
#pragma unroll
        for (int w = 0; w < 4; w++) {
            float sc = __expf(sm[w][h] - M);    // empty warp: m=-inf -> 0
            S += ss[w][h] * sc;
            A += sacc[w][c] * sc;
        }
        out[(size_t)node * 512 + c] = fmaxf(A / (S + 1e-16f) + bias[c], 0.f);
    }
}

// Layer 2 (1 head x 128 ch) + fused output head: out[node,10].
__global__ void k_fused2(const float* __restrict__ xl, const float* __restrict__ xr,
                         const int* __restrict__ rowptr, const int* __restrict__ esrc,
                         const float* __restrict__ att, const float* __restrict__ bias,
                         const float* __restrict__ oW, const float* __restrict__ ob,
                         float* __restrict__ out) {
    int node = blockIdx.x;
    int t = threadIdx.x, warp = t >> 5, lane = t & 31;
    int beg = rowptr[node], end = rowptr[node + 1];

    float xrv[4], attv[4];
    const float* pxr = xr + (size_t)node * 128;
#pragma unroll
    for (int i = 0; i < 4; i++) {
        int c = i * 32 + lane;
        xrv[i] = pxr[c];
        attv[i] = att[c];
    }
    float m = -INFINITY, s = 0.f;
    float acc[4] = {};

    for (int j = beg + warp; j < end; j += 4) {
        const float* px = xl + (size_t)esrc[j] * 128;
        float xv[4], p = 0.f;
#pragma unroll
        for (int i = 0; i < 4; i++) {
            xv[i] = px[i * 32 + lane];
            float v = xv[i] + xrv[i];
            v = v > 0.f ? v : 0.2f * v;
            p += v * attv[i];
        }
#pragma unroll
        for (int o = 16; o; o >>= 1) p += __shfl_xor_sync(0xffffffffu, p, o);
        float mn = fmaxf(m, p);
        float sc = __expf(m - mn);
        float w  = __expf(p - mn);
        s = s * sc + w;
        m = mn;
#pragma unroll
        for (int i = 0; i < 4; i++) acc[i] = acc[i] * sc + w * xv[i];
    }

    __shared__ float sm[4], ss[4];
    __shared__ float sacc[4][128];
    if (!lane) { sm[warp] = m; ss[warp] = s; }
#pragma unroll
    for (int i = 0; i < 4; i++) sacc[warp][i * 32 + lane] = acc[i];
    __syncthreads();

    float M = fmaxf(fmaxf(sm[0], sm[1]), fmaxf(sm[2], sm[3]));
    float S = 0.f, A = 0.f;
#pragma unroll
    for (int w = 0; w < 4; w++) {
        float sc = __expf(sm[w] - M);
        S += ss[w] * sc;
        A += sacc[w][t] * sc;
    }
    float o_t = A / (S + 1e-16f) + bias[t];   // hidden value, channel t

    // fused output head: out[node,o] = sum_t o_t * oW[t,o] + ob[o]
    float p[10];
#pragma unroll
    for (int o = 0; o < 10; o++) p[o] = o_t * oW[t * 10 + o];
#pragma unroll
    for (int off = 16; off; off >>= 1)
#pragma unroll
        for (int o = 0; o < 10; o++) p[o] += __shfl_xor_sync(0xffffffffu, p[o], off);
    __shared__ float pp[4][10];
    if (!lane)
#pragma unroll
        for (int o = 0; o < 10; o++) pp[warp][o] = p[o];
    __syncthreads();
    if (t < 10) {
        float v = ob[t];
#pragma unroll
        for (int w = 0; w < 4; w++) v += pp[w][t];
        out[(size_t)node * 10 + t] = v;
    }
}

// ---------------- launch ----------------------------------------------------
extern "C" void kernel_launch(void* const* d_in, const int* in_sizes, int n_in,
                              void* d_out, int out_size) {
    const float* xp   = (const float*)d_in[0];
    const int*   ei   = (const int*)  d_in[1];
    const float* emb  = (const float*)d_in[2];
    const float* pW   = (const float*)d_in[3];
    const float* pb   = (const float*)d_in[4];
    const float* W1l  = (const float*)d_in[5];
    const float* W1r  = (const float*)d_in[6];
    const float* att1 = (const float*)d_in[7];
    const float* b1   = (const float*)d_in[8];
    const float* W2l  = (const float*)d_in[9];
    const float* W2r  = (const float*)d_in[10];
    const float* att2 = (const float*)d_in[11];
    const float* b2   = (const float*)d_in[12];
    const float* oW   = (const float*)d_in[13];
    const float* ob   = (const float*)d_in[14];
    float* out = (float*)d_out;

    int n  = in_sizes[0] / 65;
    int ne = in_sizes[1] / 2;
    int et = ne + n;

    float *x0, *xl1, *xr1, *agg1, *xl2, *xr2;
    int *deg, *cursor, *rowptr, *esrc;
    cudaGetSymbolAddress((void**)&x0,   g_x0);
    cudaGetSymbolAddress((void**)&xl1,  g_xl1);
    cudaGetSymbolAddress((void**)&xr1,  g_xr1);
    cudaGetSymbolAddress((void**)&agg1, g_agg1);
    cudaGetSymbolAddress((void**)&xl2,  g_xl2);
    cudaGetSymbolAddress((void**)&xr2,  g_xr2);
    cudaGetSymbolAddress((void**)&deg,    g_deg);
    cudaGetSymbolAddress((void**)&cursor, g_cursor);
    cudaGetSymbolAddress((void**)&rowptr, g_rowptr);
    cudaGetSymbolAddress((void**)&esrc,   g_esrc);

    cudaFuncSetAttribute(k_gemm<true>,  cudaFuncAttributeMaxDynamicSharedMemorySize, GEMM_SMEM);
    cudaFuncSetAttribute(k_gemm<false>, cudaFuncAttributeMaxDynamicSharedMemorySize, GEMM_SMEM);

    const int TB = 256;
    int gm = (n + 63) / 64;

    // ---- CSR build ----
    cudaMemsetAsync(deg, 0, (size_t)(n + 1) * sizeof(int));
    cudaMemsetAsync(cursor, 0, (size_t)n * sizeof(int));
    k_hist<<<(et + TB - 1) / TB, TB>>>(ei, deg, ne, n);
    k_scan<<<1, 1024>>>(deg, rowptr, n);
    k_scatter<<<(et + TB - 1) / TB, TB>>>(ei, rowptr, cursor, esrc, ne, n);

    // ---- proj (fused embed-gather) -> x0 ----
    k_gemm<true><<<dim3(1, gm), TB, GEMM_SMEM>>>(nullptr, pW, nullptr, pb, x0, nullptr,
                                                 n, 128, 192, 1, 1, xp, emb);

    // ---- layer 1: xl1 | xr1 in one launch ----
    k_gemm<false><<<dim3(8, gm), TB, GEMM_SMEM>>>(x0, W1l, W1r, nullptr, xl1, xr1,
                                                  n, 512, 128, 0, 4, nullptr, nullptr);
    k_fused1<<<n, 128>>>(xl1, xr1, rowptr, esrc, att1, b1, agg1);

    // ---- layer 2: xl2 | xr2 in one launch ----
    k_gemm<false><<<dim3(2, gm), TB, GEMM_SMEM>>>(agg1, W2l, W2r, nullptr, xl2, xr2,
                                                  n, 128, 512, 0, 1, nullptr, nullptr);
    k_fused2<<<n, 128>>>(xl2, xr2, rowptr, esrc, att2, b2, oW, ob, out);
}